// round 2
// baseline (speedup 1.0000x reference)
#include <cuda_runtime.h>

// Problem constants
#define NROWS   4096      // b*n*h = 2*64*32
#define MID     128
#define OUTDIM  5120      // 32*32*5
#define BROW    125       // basis floats per row
#define LN_EPSF 1e-5f

// kernel 1 config
#define RPB 8

// kernel 2 config
#define MT 32             // rows per CTA
#define KC 16             // k chunk
#define NT 320            // y-cols per CTA (2 "o" blocks of 160)
#define X2SZ   (MID * MT)               // 4096 floats (X2 tile, pitch 32)
#define W3BUF  (KC * 2 * 32 * 8)        // 8192 floats per buffer (padded f8)
#define BSOFF  (X2SZ + 2 * W3BUF)       // 20480
#define SMEM_FLOATS (BSOFF + MT * 128)  // + basis tile = 24576
#define SMEM_BYTES  (SMEM_FLOATS * 4)   // 98304 B -> 2 CTAs/SM

__device__ __align__(16) float g_X2T[MID * NROWS];          // transposed X2 (2 MB)
__device__ __align__(16) float g_pw3[128 * 32 * 32 * 8];    // padded W3 (4 MB)

__device__ __forceinline__ void cp_async16(float* dst, const float* src) {
    unsigned u = (unsigned)__cvta_generic_to_shared(dst);
    asm volatile("cp.async.cg.shared.global [%0], [%1], 16;" :: "r"(u), "l"(src));
}
__device__ __forceinline__ void cp_commit() { asm volatile("cp.async.commit_group;"); }
template <int N> __device__ __forceinline__ void cp_wait() {
    asm volatile("cp.async.wait_group %0;" :: "n"(N));
}

// =====================================================================
// prep kernel: blocks [0,512) run stage1+2 -> g_X2T ; blocks [512,1024)
// pack W3 into padded [k][o][i][f8] layout (f>=5 zero).
// =====================================================================
__global__ void __launch_bounds__(128) prep_kernel(
    const float* __restrict__ feat,
    const float* __restrict__ W1, const float* __restrict__ b1,
    const float* __restrict__ g1, const float* __restrict__ be1,
    const float* __restrict__ W2, const float* __restrict__ b2,
    const float* __restrict__ g2, const float* __restrict__ be2,
    const float* __restrict__ W3)
{
    const int t = threadIdx.x;

    if (blockIdx.x >= 512) {
        // ---- pack W3 ----
        const int bid = blockIdx.x - 512;
        for (int i = bid * 128 + t; i < 128 * 32 * 32 * 8; i += 512 * 128) {
            int f = i & 7;
            int r = i >> 3;
            int ii = r & 31; r >>= 5;
            int o  = r & 31;
            int k  = r >> 5;
            g_pw3[i] = (f < 5) ? W3[k * OUTDIM + o * 160 + ii * 5 + f] : 0.0f;
        }
        return;
    }

    __shared__ float x1s[RPB][MID];
    __shared__ float redA[5][4];
    __shared__ float redB[RPB][2][4];

    const int warp = t >> 5, lane = t & 31;
    const int r0 = blockIdx.x * RPB;
    const float invM = 1.0f / (float)MID;

    // stage 1: LN(f*W1+b1) closed form in scalar f
    const float w = W1[t], b = b1[t];
    float s0 = w, s1 = b, s2 = w * w, s3 = w * b, s4 = b * b;
    #pragma unroll
    for (int o = 16; o; o >>= 1) {
        s0 += __shfl_down_sync(0xffffffffu, s0, o);
        s1 += __shfl_down_sync(0xffffffffu, s1, o);
        s2 += __shfl_down_sync(0xffffffffu, s2, o);
        s3 += __shfl_down_sync(0xffffffffu, s3, o);
        s4 += __shfl_down_sync(0xffffffffu, s4, o);
    }
    if (!lane) {
        redA[0][warp] = s0; redA[1][warp] = s1; redA[2][warp] = s2;
        redA[3][warp] = s3; redA[4][warp] = s4;
    }
    __syncthreads();
    const float Sw  = redA[0][0] + redA[0][1] + redA[0][2] + redA[0][3];
    const float Sb  = redA[1][0] + redA[1][1] + redA[1][2] + redA[1][3];
    const float Sww = redA[2][0] + redA[2][1] + redA[2][2] + redA[2][3];
    const float Swb = redA[3][0] + redA[3][1] + redA[3][2] + redA[3][3];
    const float Sbb = redA[4][0] + redA[4][1] + redA[4][2] + redA[4][3];

    const float gg = g1[t], bg = be1[t];
    #pragma unroll
    for (int r = 0; r < RPB; r++) {
        float f   = feat[r0 + r];
        float mu  = (f * Sw + Sb) * invM;
        float e2  = (f * f * Sww + 2.0f * f * Swb + Sbb) * invM;
        float var = e2 - mu * mu;
        float inv = rsqrtf(var + LN_EPSF);
        float v   = (f * w + b - mu) * inv * gg + bg;
        x1s[r][t] = fmaxf(v, 0.0f);
    }
    __syncthreads();

    // stage 2: x2 = relu(LN(x1 @ W2 + b2))
    float acc[RPB];
    #pragma unroll
    for (int r = 0; r < RPB; r++) acc[r] = 0.0f;
    #pragma unroll 4
    for (int k = 0; k < MID; k++) {
        float wv = W2[k * MID + t];
        #pragma unroll
        for (int r = 0; r < RPB; r++) acc[r] = fmaf(x1s[r][k], wv, acc[r]);
    }
    const float bb = b2[t];
    #pragma unroll
    for (int r = 0; r < RPB; r++) acc[r] += bb;

    #pragma unroll
    for (int r = 0; r < RPB; r++) {
        float v = acc[r], s = v, q = v * v;
        #pragma unroll
        for (int o = 16; o; o >>= 1) {
            s += __shfl_down_sync(0xffffffffu, s, o);
            q += __shfl_down_sync(0xffffffffu, q, o);
        }
        if (!lane) { redB[r][0][warp] = s; redB[r][1][warp] = q; }
    }
    __syncthreads();
    const float gv = g2[t], bv = be2[t];
    #pragma unroll
    for (int r = 0; r < RPB; r++) {
        float s  = redB[r][0][0] + redB[r][0][1] + redB[r][0][2] + redB[r][0][3];
        float q  = redB[r][1][0] + redB[r][1][1] + redB[r][1][2] + redB[r][1][3];
        float mu = s * invM;
        float var = q * invM - mu * mu;
        float inv = rsqrtf(var + LN_EPSF);
        float v  = (acc[r] - mu) * inv * gv + bv;
        x1s[r][t] = fmaxf(v, 0.0f);     // reuse x1s as x2 staging
    }
    __syncthreads();
    // transposed write-out: g_X2T[k][row]
    #pragma unroll
    for (int idx = t, it = 0; it < 8; it++, idx += 128) {
        int k = idx >> 3, r = idx & 7;
        g_X2T[k * NROWS + r0 + r] = x1s[r][k];
    }
}

// =====================================================================
// Kernel 2: fused GEMM (X2 @ W3 + b3) + per-row einsum + coalesced write.
// CTA: 32 rows x 320 cols. blockDim (32,8). 2 CTAs/SM.
// W3 smem layout: [k][o2][i][f8] with XOR swizzle on 16B granules:
//   granule(k,o2,i,h) stored at ((k*2+o2)*32+i)*8 + ((h ^ ((i>>2)&1))*4)
// =====================================================================
__global__ void __launch_bounds__(256, 2) fused_gemm_einsum(
    const float* __restrict__ b3,
    const float* __restrict__ basis, float* __restrict__ out)
{
    extern __shared__ float sm[];
    float* X2_s = sm;                  // [128][32]
    float* W3_s = sm + X2SZ;           // 2 x 8192
    float* B_s  = sm + BSOFF;          // [32][128]
    float* outs = sm + X2SZ;           // alias over W3_s after GEMM

    const int tx = threadIdx.x, ty = threadIdx.y;
    const int tid = ty * 32 + tx;
    const int r0  = blockIdx.y * MT;
    const int bxo = blockIdx.x;
    const int sw  = ((tx >> 2) & 1) << 2;   // swizzle offset for this lane

    // prefetch W3 chunk 0 (cp.async)
    {
        const size_t obase = 2 * (size_t)bxo;
        for (int g = tid; g < 2048; g += 256) {
            int h = g & 1, ii = (g >> 1) & 31, o2 = (g >> 6) & 1, k = g >> 7;
            float* d = W3_s + ((k * 2 + o2) * 32 + ii) * 8 + ((h ^ ((ii >> 2) & 1)) << 2);
            const float* s = g_pw3 + ((((size_t)k * 32) + (obase + o2)) * 32 + ii) * 8 + (h << 2);
            cp_async16(d, s);
        }
        cp_commit();
    }

    // load X2 tile [128 k][32 rows] (coalesced, conflict-free)
    #pragma unroll
    for (int it = 0; it < 4; it++) {
        int idx = tid + it * 256;               // 0..1023
        int k = idx >> 3, c4 = idx & 7;
        *reinterpret_cast<float4*>(&X2_s[k * 32 + c4 * 4]) =
            *reinterpret_cast<const float4*>(&g_X2T[k * NROWS + r0 + c4 * 4]);
    }
    // load basis rows
    for (int i = tid; i < MT * BROW; i += 256) {
        int r = i / BROW, j = i - r * BROW;
        B_s[r * 128 + j] = basis[(size_t)(r0 + r) * BROW + j];
    }

    float acc[4][10];
    #pragma unroll
    for (int a = 0; a < 4; a++)
        #pragma unroll
        for (int j = 0; j < 10; j++) acc[a][j] = 0.0f;

    #pragma unroll 1
    for (int c = 0; c < MID / KC; c++) {
        if (c + 1 < MID / KC) {
            float* dst = W3_s + ((c + 1) & 1) * W3BUF;
            const size_t kb = (size_t)(c + 1) * KC;
            const size_t obase = 2 * (size_t)bxo;
            for (int g = tid; g < 2048; g += 256) {
                int h = g & 1, ii = (g >> 1) & 31, o2 = (g >> 6) & 1, k = g >> 7;
                float* d = dst + ((k * 2 + o2) * 32 + ii) * 8 + ((h ^ ((ii >> 2) & 1)) << 2);
                const float* s = g_pw3 + ((((kb + k) * 32) + (obase + o2)) * 32 + ii) * 8 + (h << 2);
                cp_async16(d, s);
            }
            cp_commit();
            cp_wait<1>();
        } else {
            cp_wait<0>();
        }
        __syncthreads();

        const float* Wc = W3_s + (c & 1) * W3BUF + tx * 8;
        const float* Xc = X2_s + c * KC * 32 + ty * 4;
        #pragma unroll
        for (int kk = 0; kk < KC; kk++) {
            float4 xa = *reinterpret_cast<const float4*>(Xc + kk * 32);       // broadcast
            const float* w0p = Wc + kk * 512;
            float4 a0 = *reinterpret_cast<const float4*>(w0p + (0 ^ sw));     // o2=0, f0..3
            float4 a1 = *reinterpret_cast<const float4*>(w0p + (4 ^ sw));     // o2=0, f4
            float4 c0 = *reinterpret_cast<const float4*>(w0p + 256 + (0 ^ sw)); // o2=1, f0..3
            float4 c1 = *reinterpret_cast<const float4*>(w0p + 256 + (4 ^ sw)); // o2=1, f4
            float wb[10] = {a0.x, a0.y, a0.z, a0.w, a1.x,
                            c0.x, c0.y, c0.z, c0.w, c1.x};
            float xr[4] = {xa.x, xa.y, xa.z, xa.w};
            #pragma unroll
            for (int rr = 0; rr < 4; rr++)
                #pragma unroll
                for (int j = 0; j < 10; j++)
                    acc[rr][j] = fmaf(xr[rr], wb[j], acc[rr][j]);
        }
        __syncthreads();
    }

    // add b3
    {
        const float* b3c = b3 + bxo * 320;
        float bb[10];
        #pragma unroll
        for (int o2 = 0; o2 < 2; o2++)
            #pragma unroll
            for (int f = 0; f < 5; f++) bb[o2 * 5 + f] = b3c[o2 * 160 + tx * 5 + f];
        #pragma unroll
        for (int rr = 0; rr < 4; rr++)
            #pragma unroll
            for (int j = 0; j < 10; j++) acc[rr][j] += bb[j];
    }

    // einsum + coalesced writeout (4 batches of 8 rows)
    #pragma unroll 1
    for (int bt = 0; bt < 4; bt++) {
        const float* Br = B_s + (ty * 4 + bt) * 128;
        #pragma unroll
        for (int d = 0; d < 5; d++) {
            #pragma unroll
            for (int m = 0; m < 5; m++) {
                float v0 = 0.0f, v1 = 0.0f;
                #pragma unroll
                for (int f = 0; f < 5; f++) {
                    float bf = Br[d * 25 + m * 5 + f];   // broadcast
                    v0 = fmaf(acc[bt][f],     bf, v0);
                    v1 = fmaf(acc[bt][5 + f], bf, v1);
                }
                outs[(ty * 10 + d)     * 160 + tx * 5 + m] = v0;
                outs[(ty * 10 + 5 + d) * 160 + tx * 5 + m] = v1;
            }
        }
        __syncthreads();
        for (int i2 = tid; i2 < 3200; i2 += 256) {
            int lr  = i2 / 400;
            int rem = i2 - lr * 400;
            int od  = rem / 40, c4 = rem - od * 40;
            int gr  = r0 + lr * 4 + bt;
            *reinterpret_cast<float4*>(
                &out[(size_t)gr * (160 * 160) + (bxo * 10 + od) * 160 + c4 * 4]) =
                *reinterpret_cast<const float4*>(&outs[(lr * 10 + od) * 160 + c4 * 4]);
        }
        __syncthreads();
    }
}

extern "C" void kernel_launch(void* const* d_in, const int* in_sizes, int n_in,
                              void* d_out, int out_size)
{
    const float* feat  = (const float*)d_in[0];
    const float* basis = (const float*)d_in[1];
    const float* W1    = (const float*)d_in[2];
    const float* b1    = (const float*)d_in[3];
    const float* g1    = (const float*)d_in[4];
    const float* be1   = (const float*)d_in[5];
    const float* W2    = (const float*)d_in[6];
    const float* b2    = (const float*)d_in[7];
    const float* g2    = (const float*)d_in[8];
    const float* be2   = (const float*)d_in[9];
    const float* W3    = (const float*)d_in[10];
    const float* b3    = (const float*)d_in[11];
    float* out = (float*)d_out;

    prep_kernel<<<1024, 128>>>(feat, W1, b1, g1, be1, W2, b2, g2, be2, W3);

    static int smem_set = 0;
    if (!smem_set) {
        cudaFuncSetAttribute(fused_gemm_einsum,
                             cudaFuncAttributeMaxDynamicSharedMemorySize, SMEM_BYTES);
        smem_set = 1;
    }
    dim3 grid(OUTDIM / NT, NROWS / MT);   // (16, 128)
    dim3 blk(32, 8);
    fused_gemm_einsum<<<grid, blk, SMEM_BYTES>>>(b3, basis, out);
}

// round 8
// speedup vs baseline: 1.2142x; 1.2142x over previous
#include <cuda_runtime.h>
#include <cuda_bf16.h>
#include <cstdint>

// ---------------- problem constants ----------------
#define NROWS   4096
#define MID     128
#define OUTDIM  5120
#define BROW    125
#define LN_EPSF 1e-5f
#define RPB     8

#define MTILES  (NROWS / 128)    // 32 row tiles
#define NOBLK   32               // o blocks (160 cols each)

// ---- smem layout (bytes) for gemm kernel ----
#define OFF_A_HI   0            // 32768  (128 x 128 bf16, swizzled)
#define OFF_A_LO   32768        // 32768
#define OFF_B_HI   65536        // 40960  (160 x 128 bf16, swizzled)
#define OFF_B_LO   106496       // 40960   -> operands end 147456
#define OFF_STG    0            // staging aliases operands: 128*165*4 = 84480
#define OFF_BAS    147456       // 128*125*4 = 64000
#define OFF_B3     211456       // 160*4 = 640
#define SMEM_TOTAL 212096
#define SP         165          // staging pitch (floats): conflict-free

// packed pre-swizzled operand images
__device__ __align__(16) __nv_bfloat16 g_Ahi[MTILES * 128 * 128];
__device__ __align__(16) __nv_bfloat16 g_Alo[MTILES * 128 * 128];
__device__ __align__(16) __nv_bfloat16 g_Bhi[NOBLK * 160 * 128];
__device__ __align__(16) __nv_bfloat16 g_Blo[NOBLK * 160 * 128];

// ---------------- helpers ----------------
__device__ __forceinline__ uint32_t smem_u32(const void* p) {
    uint32_t a;
    asm("{ .reg .u64 t; cvta.to.shared.u64 t, %1; cvt.u32.u64 %0, t; }" : "=r"(a) : "l"(p));
    return a;
}
__device__ __forceinline__ void cp_async16(uint32_t dst, const void* src) {
    asm volatile("cp.async.cg.shared.global [%0], [%1], 16;" :: "r"(dst), "l"(src));
}
__device__ __forceinline__ void cp_commit() { asm volatile("cp.async.commit_group;"); }
__device__ __forceinline__ void cp_wait0() { asm volatile("cp.async.wait_group 0;"); }

__device__ __forceinline__ void ldmx4(uint32_t* r, uint32_t addr) {
    asm volatile("ldmatrix.sync.aligned.m8n8.x4.shared.b16 {%0,%1,%2,%3}, [%4];"
                 : "=r"(r[0]), "=r"(r[1]), "=r"(r[2]), "=r"(r[3]) : "r"(addr));
}
__device__ __forceinline__ void mma16816(float* c, const uint32_t* a,
                                         uint32_t b0, uint32_t b1) {
    asm volatile(
        "mma.sync.aligned.m16n8k16.row.col.f32.bf16.bf16.f32 "
        "{%0,%1,%2,%3},{%4,%5,%6,%7},{%8,%9},{%0,%1,%2,%3};"
        : "+f"(c[0]), "+f"(c[1]), "+f"(c[2]), "+f"(c[3])
        : "r"(a[0]), "r"(a[1]), "r"(a[2]), "r"(a[3]), "r"(b0), "r"(b1));
}

// swizzled element index inside a [row][k=128] bf16 tile:
//   idx = row*128 + (((k>>3) ^ (row&7))<<3) + (k&7)
__device__ __forceinline__ int swz_idx(int row, int k) {
    return row * 128 + ((((k >> 3) ^ (row & 7)) << 3) | (k & 7));
}

// =====================================================================
// prep kernel: blocks [0,512): stage1+2 -> A hi/lo images
//              blocks [512,1024): pack W3 -> B hi/lo images
// =====================================================================
__global__ void __launch_bounds__(128) prep_kernel(
    const float* __restrict__ feat,
    const float* __restrict__ W1, const float* __restrict__ b1,
    const float* __restrict__ g1, const float* __restrict__ be1,
    const float* __restrict__ W2, const float* __restrict__ b2,
    const float* __restrict__ g2, const float* __restrict__ be2,
    const float* __restrict__ W3)
{
    const int t = threadIdx.x;

    if (blockIdx.x >= 512) {
        // B pack: e -> (o, n, k)
        for (int e = (blockIdx.x - 512) * 128 + t; e < NOBLK * 160 * 128;
             e += 512 * 128) {
            int k = e & 127;
            int r = e >> 7;
            int n = r % 160;
            int o = r / 160;
            float v = W3[(size_t)k * OUTDIM + o * 160 + n];
            int idx = o * 20480 + swz_idx(n, k);
            __nv_bfloat16 h = __float2bfloat16(v);
            g_Bhi[idx] = h;
            g_Blo[idx] = __float2bfloat16(v - __bfloat162float(h));
        }
        return;
    }

    __shared__ float x1s[RPB][MID];
    __shared__ float redA[5][4];
    __shared__ float redB[RPB][2][4];

    const int warp = t >> 5, lane = t & 31;
    const int r0 = blockIdx.x * RPB;
    const float invM = 1.0f / (float)MID;

    // stage 1: LN(f*W1+b1) closed form in scalar f
    const float w = W1[t], b = b1[t];
    float s0 = w, s1 = b, s2 = w * w, s3 = w * b, s4 = b * b;
    #pragma unroll
    for (int o = 16; o; o >>= 1) {
        s0 += __shfl_down_sync(0xffffffffu, s0, o);
        s1 += __shfl_down_sync(0xffffffffu, s1, o);
        s2 += __shfl_down_sync(0xffffffffu, s2, o);
        s3 += __shfl_down_sync(0xffffffffu, s3, o);
        s4 += __shfl_down_sync(0xffffffffu, s4, o);
    }
    if (!lane) {
        redA[0][warp] = s0; redA[1][warp] = s1; redA[2][warp] = s2;
        redA[3][warp] = s3; redA[4][warp] = s4;
    }
    __syncthreads();
    const float Sw  = redA[0][0] + redA[0][1] + redA[0][2] + redA[0][3];
    const float Sb  = redA[1][0] + redA[1][1] + redA[1][2] + redA[1][3];
    const float Sww = redA[2][0] + redA[2][1] + redA[2][2] + redA[2][3];
    const float Swb = redA[3][0] + redA[3][1] + redA[3][2] + redA[3][3];
    const float Sbb = redA[4][0] + redA[4][1] + redA[4][2] + redA[4][3];

    const float gg = g1[t], bg = be1[t];
    #pragma unroll
    for (int r = 0; r < RPB; r++) {
        float f   = feat[r0 + r];
        float mu  = (f * Sw + Sb) * invM;
        float e2  = (f * f * Sww + 2.0f * f * Swb + Sbb) * invM;
        float inv = rsqrtf(e2 - mu * mu + LN_EPSF);
        x1s[r][t] = fmaxf((f * w + b - mu) * inv * gg + bg, 0.0f);
    }
    __syncthreads();

    // stage 2
    float acc[RPB];
    #pragma unroll
    for (int r = 0; r < RPB; r++) acc[r] = 0.0f;
    #pragma unroll 4
    for (int k = 0; k < MID; k++) {
        float wv = W2[k * MID + t];
        #pragma unroll
        for (int r = 0; r < RPB; r++) acc[r] = fmaf(x1s[r][k], wv, acc[r]);
    }
    const float bb2 = b2[t];
    #pragma unroll
    for (int r = 0; r < RPB; r++) acc[r] += bb2;

    #pragma unroll
    for (int r = 0; r < RPB; r++) {
        float v = acc[r], s = v, q = v * v;
        #pragma unroll
        for (int o = 16; o; o >>= 1) {
            s += __shfl_down_sync(0xffffffffu, s, o);
            q += __shfl_down_sync(0xffffffffu, q, o);
        }
        if (!lane) { redB[r][0][warp] = s; redB[r][1][warp] = q; }
    }
    __syncthreads();
    const float gv = g2[t], bv = be2[t];
    #pragma unroll
    for (int r = 0; r < RPB; r++) {
        float s  = redB[r][0][0] + redB[r][0][1] + redB[r][0][2] + redB[r][0][3];
        float q  = redB[r][1][0] + redB[r][1][1] + redB[r][1][2] + redB[r][1][3];
        float mu = s * invM;
        float inv = rsqrtf(q * invM - mu * mu + LN_EPSF);
        float v  = fmaxf((acc[r] - mu) * inv * gv + bv, 0.0f);
        int m = r0 + r;
        int tile = m >> 7, ml = m & 127;
        int idx = tile * 16384 + swz_idx(ml, t);
        __nv_bfloat16 h = __float2bfloat16(v);
        g_Ahi[idx] = h;
        g_Alo[idx] = __float2bfloat16(v - __bfloat162float(h));
    }
}

// =====================================================================
// GEMM (bf16x3 mma.sync) + einsum epilogue.
// grid (32 o-blocks, 32 rowtiles), 256 threads.
// Warp partition: 4 m-groups (2 mtiles = 32 rows) x 2 n-halves (10 ntiles).
// =====================================================================
__global__ void __launch_bounds__(256)
gemm_einsum_mma(const float* __restrict__ b3,
                const float* __restrict__ basis,
                float* __restrict__ out)
{
    extern __shared__ __align__(16) char smem[];
    const uint32_t sb = smem_u32(smem);
    const int tid  = threadIdx.x;
    const int wid  = tid >> 5, lane = tid & 31;
    const int ob   = blockIdx.x;          // o block (0..31)
    const int rt   = blockIdx.y;          // row tile (0..31)
    const int r0   = rt * 128;

    // ---- cp.async: A hi/lo, B hi/lo, basis, b3
    {
        const char* sAh = (const char*)(g_Ahi + (size_t)rt * 16384);
        const char* sAl = (const char*)(g_Alo + (size_t)rt * 16384);
        const char* sBh = (const char*)(g_Bhi + (size_t)ob * 20480);
        const char* sBl = (const char*)(g_Blo + (size_t)ob * 20480);
        for (int i = tid; i < 2048; i += 256) {
            cp_async16(sb + OFF_A_HI + i * 16, sAh + i * 16);
            cp_async16(sb + OFF_A_LO + i * 16, sAl + i * 16);
        }
        for (int i = tid; i < 2560; i += 256) {
            cp_async16(sb + OFF_B_HI + i * 16, sBh + i * 16);
            cp_async16(sb + OFF_B_LO + i * 16, sBl + i * 16);
        }
        const char* bas = (const char*)(basis + (size_t)r0 * BROW);
        for (int i = tid; i < 4000; i += 256)
            cp_async16(sb + OFF_BAS + i * 16, bas + i * 16);
        const char* b3p = (const char*)(b3 + ob * 160);
        if (tid < 40) cp_async16(sb + OFF_B3 + tid * 16, b3p + tid * 16);
        cp_commit();
    }
    cp_wait0();
    __syncthreads();

    // ---- MMA mainloop ----
    const int mg = wid >> 1;              // m-group 0..3 (mtiles 2mg, 2mg+1)
    const int wn = wid & 1;               // n-half: 80 n-rows each
    const int axor = lane & 7;
    const int ak   = lane >> 4;           // A k-half select bit
    const int bk   = (lane >> 3) & 1;     // B k-half select bit

    const uint32_t aAddr0 = sb + OFF_A_HI + ((mg * 32 + (lane & 15)) << 8);
    const uint32_t aAddr1 = aAddr0 + (16 << 8);
    const uint32_t bAddr0 = sb + OFF_B_HI +
        ((wn * 80 + ((lane >> 4) & 1) * 8 + (lane & 7)) << 8);   // FIX: 80 rows/half

    float c[2][10][4];
    #pragma unroll
    for (int a = 0; a < 2; a++)
        #pragma unroll
        for (int n = 0; n < 10; n++)
            #pragma unroll
            for (int q = 0; q < 4; q++) c[a][n][q] = 0.0f;

    #pragma unroll
    for (int kk = 0; kk < 8; kk++) {
        uint32_t gA = (uint32_t)(((2 * kk + ak) ^ axor) << 4);
        uint32_t gB = (uint32_t)(((2 * kk + bk) ^ axor) << 4);
        uint32_t ah0[4], al0[4], ah1[4], al1[4];
        ldmx4(ah0, aAddr0 + gA);
        ldmx4(al0, aAddr0 + 32768 + gA);
        ldmx4(ah1, aAddr1 + gA);
        ldmx4(al1, aAddr1 + 32768 + gA);
        #pragma unroll
        for (int j2 = 0; j2 < 5; j2++) {
            uint32_t bh[4], bl[4];
            uint32_t ba = bAddr0 + j2 * 4096 + gB;
            ldmx4(bh, ba);
            ldmx4(bl, ba + 40960);
            // mtile 0
            mma16816(c[0][2 * j2], ah0, bh[0], bh[1]);
            mma16816(c[0][2 * j2], ah0, bl[0], bl[1]);
            mma16816(c[0][2 * j2], al0, bh[0], bh[1]);
            mma16816(c[0][2 * j2 + 1], ah0, bh[2], bh[3]);
            mma16816(c[0][2 * j2 + 1], ah0, bl[2], bl[3]);
            mma16816(c[0][2 * j2 + 1], al0, bh[2], bh[3]);
            // mtile 1
            mma16816(c[1][2 * j2], ah1, bh[0], bh[1]);
            mma16816(c[1][2 * j2], ah1, bl[0], bl[1]);
            mma16816(c[1][2 * j2], al1, bh[0], bh[1]);
            mma16816(c[1][2 * j2 + 1], ah1, bh[2], bh[3]);
            mma16816(c[1][2 * j2 + 1], ah1, bl[2], bl[3]);
            mma16816(c[1][2 * j2 + 1], al1, bh[2], bh[3]);
        }
    }

    __syncthreads();   // operands dead; staging may now overwrite them

    // ---- stage C (+b3) to smem [128][SP]
    float* stg = (float*)(smem + OFF_STG);
    const float* sB3 = (const float*)(smem + OFF_B3);
    {
        const int rlo0 = mg * 32 + (lane >> 2);
        #pragma unroll
        for (int mtl = 0; mtl < 2; mtl++) {
            int rlo = rlo0 + mtl * 16;
            int rhi = rlo + 8;
            #pragma unroll
            for (int ntl = 0; ntl < 10; ntl++) {
                int col = (wn * 10 + ntl) * 8 + 2 * (lane & 3);
                float bA = sB3[col], bB = sB3[col + 1];
                stg[rlo * SP + col]     = c[mtl][ntl][0] + bA;
                stg[rlo * SP + col + 1] = c[mtl][ntl][1] + bB;
                stg[rhi * SP + col]     = c[mtl][ntl][2] + bA;
                stg[rhi * SP + col + 1] = c[mtl][ntl][3] + bB;
            }
        }
    }
    __syncthreads();

    // ---- einsum epilogue: warp = (rowgroup, i-half); lane = row
    const int rg    = wid >> 1;
    const int ihalf = wid & 1;
    const int rloc  = rg * 32 + lane;
    const float* Bp = (const float*)(smem + OFF_BAS) + rloc * BROW;
    const float* Rp = stg + rloc * SP + ihalf * 80;

    float Rv[80];
    #pragma unroll
    for (int t2 = 0; t2 < 80; t2++) Rv[t2] = Rp[t2];

    float* obase = out + (size_t)(r0 + rloc) * 25600 + (size_t)ob * 5 * 160 +
                   ihalf * 80;
    #pragma unroll 1
    for (int d = 0; d < 5; d++) {
        float bb[25];
        #pragma unroll
        for (int q = 0; q < 25; q++) bb[q] = Bp[d * 25 + q];
        float* od = obase + d * 160;
        #pragma unroll
        for (int t4 = 0; t4 < 20; t4++) {
            float4 v;
            float vv[4];
            #pragma unroll
            for (int u = 0; u < 4; u++) {
                int t2 = t4 * 4 + u;
                int i2 = t2 / 5, m = t2 % 5;
                float a = Rv[i2 * 5] * bb[m * 5];
                a = fmaf(Rv[i2 * 5 + 1], bb[m * 5 + 1], a);
                a = fmaf(Rv[i2 * 5 + 2], bb[m * 5 + 2], a);
                a = fmaf(Rv[i2 * 5 + 3], bb[m * 5 + 3], a);
                a = fmaf(Rv[i2 * 5 + 4], bb[m * 5 + 4], a);
                vv[u] = a;
            }
            v.x = vv[0]; v.y = vv[1]; v.z = vv[2]; v.w = vv[3];
            *reinterpret_cast<float4*>(od + t4 * 4) = v;
        }
    }
}

extern "C" void kernel_launch(void* const* d_in, const int* in_sizes, int n_in,
                              void* d_out, int out_size)
{
    const float* feat  = (const float*)d_in[0];
    const float* basis = (const float*)d_in[1];
    const float* W1    = (const float*)d_in[2];
    const float* b1    = (const float*)d_in[3];
    const float* g1    = (const float*)d_in[4];
    const float* be1   = (const float*)d_in[5];
    const float* W2    = (const float*)d_in[6];
    const float* b2    = (const float*)d_in[7];
    const float* g2    = (const float*)d_in[8];
    const float* be2   = (const float*)d_in[9];
    const float* W3    = (const float*)d_in[10];
    const float* b3    = (const float*)d_in[11];
    float* out = (float*)d_out;

    prep_kernel<<<1024, 128>>>(feat, W1, b1, g1, be1, W2, b2, g2, be2, W3);

    cudaFuncSetAttribute(gemm_einsum_mma,
                         cudaFuncAttributeMaxDynamicSharedMemorySize, SMEM_TOTAL);
    dim3 grid(NOBLK, MTILES);   // (32, 32)
    gemm_einsum_mma<<<grid, 256, SMEM_TOTAL>>>(b3, basis, out);
}

// round 11
// speedup vs baseline: 1.2403x; 1.0215x over previous
#include <cuda_runtime.h>
#include <cuda_bf16.h>
#include <cstdint>

// ---------------- problem constants ----------------
#define NROWS   4096
#define MID     128
#define OUTDIM  5120
#define BROW    125
#define LN_EPSF 1e-5f
#define RPB     8

#define MTILES  (NROWS / 128)    // 32 row tiles
#define NOBLK   32               // o blocks (160 cols each)

// ---- smem layout (bytes) for gemm kernel ----
#define OFF_A_HI   0            // 32768  (128 x 128 bf16, swizzled)
#define OFF_A_LO   32768        // 32768
#define OFF_B_HI   65536        // 40960  (160 x 128 bf16, swizzled)
#define OFF_B_LO   106496       // 40960   -> operands end 147456
#define OFF_STG    0            // staging aliases operands: 128*165*4 = 84480
#define OFF_BAS    147456       // 128*125*4 = 64000
#define OFF_B3     211456       // 160*4 = 640
#define SMEM_TOTAL 212096
#define SP         165          // staging pitch (floats): conflict-free

// packW3 kernel smem: [128][161] f32
#define PK_PITCH   161
#define PK_SMEM    (128 * PK_PITCH * 4)   // 82432

// packed pre-swizzled operand images
__device__ __align__(16) __nv_bfloat16 g_Ahi[MTILES * 128 * 128];
__device__ __align__(16) __nv_bfloat16 g_Alo[MTILES * 128 * 128];
__device__ __align__(16) __nv_bfloat16 g_Bhi[NOBLK * 160 * 128];
__device__ __align__(16) __nv_bfloat16 g_Blo[NOBLK * 160 * 128];

// ---------------- helpers ----------------
__device__ __forceinline__ uint32_t smem_u32(const void* p) {
    uint32_t a;
    asm("{ .reg .u64 t; cvta.to.shared.u64 t, %1; cvt.u32.u64 %0, t; }" : "=r"(a) : "l"(p));
    return a;
}
__device__ __forceinline__ void cp_async16(uint32_t dst, const void* src) {
    asm volatile("cp.async.cg.shared.global [%0], [%1], 16;" :: "r"(dst), "l"(src));
}
__device__ __forceinline__ void cp_commit() { asm volatile("cp.async.commit_group;"); }
template <int N> __device__ __forceinline__ void cp_wait() {
    asm volatile("cp.async.wait_group %0;" :: "n"(N));
}

__device__ __forceinline__ void ldmx4(uint32_t* r, uint32_t addr) {
    asm volatile("ldmatrix.sync.aligned.m8n8.x4.shared.b16 {%0,%1,%2,%3}, [%4];"
                 : "=r"(r[0]), "=r"(r[1]), "=r"(r[2]), "=r"(r[3]) : "r"(addr));
}
__device__ __forceinline__ void mma16816(float* c, const uint32_t* a,
                                         uint32_t b0, uint32_t b1) {
    asm volatile(
        "mma.sync.aligned.m16n8k16.row.col.f32.bf16.bf16.f32 "
        "{%0,%1,%2,%3},{%4,%5,%6,%7},{%8,%9},{%0,%1,%2,%3};"
        : "+f"(c[0]), "+f"(c[1]), "+f"(c[2]), "+f"(c[3])
        : "r"(a[0]), "r"(a[1]), "r"(a[2]), "r"(a[3]), "r"(b0), "r"(b1));
}

// swizzled element index inside a [row][k=128] bf16 tile
__device__ __forceinline__ int swz_idx(int row, int k) {
    return row * 128 + ((((k >> 3) ^ (row & 7)) << 3) | (k & 7));
}

// =====================================================================
// stage12 kernel: LN/matvec/LN -> packed bf16 hi/lo A images
// =====================================================================
__global__ void __launch_bounds__(128) stage12_kernel(
    const float* __restrict__ feat,
    const float* __restrict__ W1, const float* __restrict__ b1,
    const float* __restrict__ g1, const float* __restrict__ be1,
    const float* __restrict__ W2, const float* __restrict__ b2,
    const float* __restrict__ g2, const float* __restrict__ be2)
{
    const int t = threadIdx.x;
    __shared__ float x1s[RPB][MID];
    __shared__ float redA[5][4];
    __shared__ float redB[RPB][2][4];

    const int warp = t >> 5, lane = t & 31;
    const int r0 = blockIdx.x * RPB;
    const float invM = 1.0f / (float)MID;

    const float w = W1[t], b = b1[t];
    float s0 = w, s1 = b, s2 = w * w, s3 = w * b, s4 = b * b;
    #pragma unroll
    for (int o = 16; o; o >>= 1) {
        s0 += __shfl_down_sync(0xffffffffu, s0, o);
        s1 += __shfl_down_sync(0xffffffffu, s1, o);
        s2 += __shfl_down_sync(0xffffffffu, s2, o);
        s3 += __shfl_down_sync(0xffffffffu, s3, o);
        s4 += __shfl_down_sync(0xffffffffu, s4, o);
    }
    if (!lane) {
        redA[0][warp] = s0; redA[1][warp] = s1; redA[2][warp] = s2;
        redA[3][warp] = s3; redA[4][warp] = s4;
    }
    __syncthreads();
    const float Sw  = redA[0][0] + redA[0][1] + redA[0][2] + redA[0][3];
    const float Sb  = redA[1][0] + redA[1][1] + redA[1][2] + redA[1][3];
    const float Sww = redA[2][0] + redA[2][1] + redA[2][2] + redA[2][3];
    const float Swb = redA[3][0] + redA[3][1] + redA[3][2] + redA[3][3];
    const float Sbb = redA[4][0] + redA[4][1] + redA[4][2] + redA[4][3];

    const float gg = g1[t], bg = be1[t];
    #pragma unroll
    for (int r = 0; r < RPB; r++) {
        float f   = feat[r0 + r];
        float mu  = (f * Sw + Sb) * invM;
        float e2  = (f * f * Sww + 2.0f * f * Swb + Sbb) * invM;
        float inv = rsqrtf(e2 - mu * mu + LN_EPSF);
        x1s[r][t] = fmaxf((f * w + b - mu) * inv * gg + bg, 0.0f);
    }
    __syncthreads();

    float acc[RPB];
    #pragma unroll
    for (int r = 0; r < RPB; r++) acc[r] = 0.0f;
    #pragma unroll 4
    for (int k = 0; k < MID; k++) {
        float wv = W2[k * MID + t];
        #pragma unroll
        for (int r = 0; r < RPB; r++) acc[r] = fmaf(x1s[r][k], wv, acc[r]);
    }
    const float bb2 = b2[t];
    #pragma unroll
    for (int r = 0; r < RPB; r++) acc[r] += bb2;

    #pragma unroll
    for (int r = 0; r < RPB; r++) {
        float v = acc[r], s = v, q = v * v;
        #pragma unroll
        for (int o = 16; o; o >>= 1) {
            s += __shfl_down_sync(0xffffffffu, s, o);
            q += __shfl_down_sync(0xffffffffu, q, o);
        }
        if (!lane) { redB[r][0][warp] = s; redB[r][1][warp] = q; }
    }
    __syncthreads();
    const float gv = g2[t], bv = be2[t];
    #pragma unroll
    for (int r = 0; r < RPB; r++) {
        float s  = redB[r][0][0] + redB[r][0][1] + redB[r][0][2] + redB[r][0][3];
        float q  = redB[r][1][0] + redB[r][1][1] + redB[r][1][2] + redB[r][1][3];
        float mu = s * invM;
        float inv = rsqrtf(q * invM - mu * mu + LN_EPSF);
        float v  = fmaxf((acc[r] - mu) * inv * gv + bv, 0.0f);
        int m = r0 + r;
        int tile = m >> 7, ml = m & 127;
        int idx = tile * 16384 + swz_idx(ml, t);
        __nv_bfloat16 h = __float2bfloat16(v);
        g_Ahi[idx] = h;
        g_Alo[idx] = __float2bfloat16(v - __bfloat162float(h));
    }
}

// =====================================================================
// packW3: per o-block, stage W3 chunk through smem (coalesced LDG),
// write swizzled hi/lo images with fully linear uint32 stores.
// =====================================================================
__global__ void __launch_bounds__(256) packW3_kernel(const float* __restrict__ W3)
{
    extern __shared__ float sw[];     // [128][PK_PITCH]
    const int o = blockIdx.x, t = threadIdx.x;

    for (int i = t; i < 128 * 160; i += 256) {
        int k = i / 160, n = i - k * 160;          // consecutive t -> consecutive n
        sw[k * PK_PITCH + n] = W3[(size_t)k * OUTDIM + o * 160 + n];
    }
    __syncthreads();

    uint32_t* bh = (uint32_t*)g_Bhi + o * 10240;
    uint32_t* bl = (uint32_t*)g_Blo + o * 10240;
    for (int i = t; i < 10240; i += 256) {
        int n = i >> 6, wq = i & 63;
        int q = 2 * wq;
        int k = (((q >> 3) ^ (n & 7)) << 3) | (q & 7);   // inverse swizzle
        float v0 = sw[k * PK_PITCH + n];
        float v1 = sw[(k + 1) * PK_PITCH + n];
        __nv_bfloat16 h0 = __float2bfloat16(v0), h1 = __float2bfloat16(v1);
        __nv_bfloat16 l0 = __float2bfloat16(v0 - __bfloat162float(h0));
        __nv_bfloat16 l1 = __float2bfloat16(v1 - __bfloat162float(h1));
        bh[i] = (uint32_t)__bfloat16_as_ushort(h0) |
                ((uint32_t)__bfloat16_as_ushort(h1) << 16);
        bl[i] = (uint32_t)__bfloat16_as_ushort(l0) |
                ((uint32_t)__bfloat16_as_ushort(l1) << 16);
    }
}

// =====================================================================
// GEMM (bf16x3 mma.sync) + einsum epilogue. 512 threads, 16 warps.
// Mainloop: warp = (mtile mg 0..7) x (n-half wn 0..1, 80 cols).
// =====================================================================
__global__ void __launch_bounds__(512, 1)
gemm_einsum_mma(const float* __restrict__ b3,
                const float* __restrict__ basis,
                float* __restrict__ out)
{
    extern __shared__ __align__(16) char smem[];
    const uint32_t sb = smem_u32(smem);
    const int tid  = threadIdx.x;
    const int wid  = tid >> 5, lane = tid & 31;
    const int ob   = blockIdx.x;          // o block (0..31)
    const int rt   = blockIdx.y;          // row tile (0..31)
    const int r0   = rt * 128;

    // ---- group 0: A hi/lo + B hi/lo
    {
        const char* sAh = (const char*)(g_Ahi + (size_t)rt * 16384);
        const char* sAl = (const char*)(g_Alo + (size_t)rt * 16384);
        const char* sBh = (const char*)(g_Bhi + (size_t)ob * 20480);
        const char* sBl = (const char*)(g_Blo + (size_t)ob * 20480);
        for (int i = tid; i < 2048; i += 512) {
            cp_async16(sb + OFF_A_HI + i * 16, sAh + i * 16);
            cp_async16(sb + OFF_A_LO + i * 16, sAl + i * 16);
        }
        for (int i = tid; i < 2560; i += 512) {
            cp_async16(sb + OFF_B_HI + i * 16, sBh + i * 16);
            cp_async16(sb + OFF_B_LO + i * 16, sBl + i * 16);
        }
        cp_commit();
    }
    // ---- group 1: basis + b3 (only needed by epilogue)
    {
        const char* bas = (const char*)(basis + (size_t)r0 * BROW);
        for (int i = tid; i < 4000; i += 512)
            cp_async16(sb + OFF_BAS + i * 16, bas + i * 16);
        const char* b3p = (const char*)(b3 + ob * 160);
        if (tid < 40) cp_async16(sb + OFF_B3 + tid * 16, b3p + tid * 16);
        cp_commit();
    }
    cp_wait<1>();        // operands ready; basis may still be in flight
    __syncthreads();

    // ---- MMA mainloop ----
    const int mg = wid >> 1;              // mtile 0..7 (16 rows)
    const int wn = wid & 1;               // n-half (80 cols)
    const int axor = lane & 7;
    const int ak   = lane >> 4;
    const int bk   = (lane >> 3) & 1;

    const uint32_t aAddr = sb + OFF_A_HI + ((mg * 16 + (lane & 15)) << 8);
    const uint32_t bAddr0 = sb + OFF_B_HI +
        ((wn * 80 + ((lane >> 4) & 1) * 8 + (lane & 7)) << 8);

    float c[10][4];
    #pragma unroll
    for (int n = 0; n < 10; n++)
        #pragma unroll
        for (int q = 0; q < 4; q++) c[n][q] = 0.0f;

    #pragma unroll
    for (int kk = 0; kk < 8; kk++) {
        uint32_t gA = (uint32_t)(((2 * kk + ak) ^ axor) << 4);
        uint32_t gB = (uint32_t)(((2 * kk + bk) ^ axor) << 4);
        uint32_t ah[4], al[4];
        ldmx4(ah, aAddr + gA);
        ldmx4(al, aAddr + 32768 + gA);
        #pragma unroll
        for (int j2 = 0; j2 < 5; j2++) {
            uint32_t bh[4], bl[4];
            uint32_t ba = bAddr0 + j2 * 4096 + gB;
            ldmx4(bh, ba);
            ldmx4(bl, ba + 40960);
            mma16816(c[2 * j2], ah, bh[0], bh[1]);
            mma16816(c[2 * j2], ah, bl[0], bl[1]);
            mma16816(c[2 * j2], al, bh[0], bh[1]);
            mma16816(c[2 * j2 + 1], ah, bh[2], bh[3]);
            mma16816(c[2 * j2 + 1], ah, bl[2], bl[3]);
            mma16816(c[2 * j2 + 1], al, bh[2], bh[3]);
        }
    }

    __syncthreads();   // operands dead; staging may overwrite them

    // ---- stage C to smem [128][SP] (no b3 here — added in epilogue)
    float* stg = (float*)(smem + OFF_STG);
    {
        const int rlo = mg * 16 + (lane >> 2);
        const int rhi = rlo + 8;
        #pragma unroll
        for (int ntl = 0; ntl < 10; ntl++) {
            int col = (wn * 10 + ntl) * 8 + 2 * (lane & 3);
            stg[rlo * SP + col]     = c[ntl][0];
            stg[rlo * SP + col + 1] = c[ntl][1];
            stg[rhi * SP + col]     = c[ntl][2];
            stg[rhi * SP + col + 1] = c[ntl][3];
        }
    }
    cp_wait<0>();        // basis + b3 now required
    __syncthreads();

    // ---- einsum epilogue: warp = (rowgroup rg 0..3, i-quarter iq 0..3)
    const int rg    = wid >> 2;
    const int iq    = wid & 3;
    const int rloc  = rg * 32 + lane;
    const float* Bp  = (const float*)(smem + OFF_BAS) + rloc * BROW;
    const float* sB3 = (const float*)(smem + OFF_B3) + iq * 40;
    const float* Rp  = stg + rloc * SP + iq * 40;

    float Rv[40];
    #pragma unroll
    for (int t2 = 0; t2 < 40; t2++) Rv[t2] = Rp[t2] + sB3[t2];

    float* obase = out + (size_t)(r0 + rloc) * 25600 + (size_t)ob * 800 + iq * 40;
    #pragma unroll 1
    for (int d = 0; d < 5; d++) {
        float bb[25];
        #pragma unroll
        for (int q = 0; q < 25; q++) bb[q] = Bp[d * 25 + q];
        float* od = obase + d * 160;
        #pragma unroll
        for (int t4 = 0; t4 < 10; t4++) {
            float vv[4];
            #pragma unroll
            for (int u = 0; u < 4; u++) {
                int t2 = t4 * 4 + u;
                int i2 = t2 / 5, m = t2 % 5;
                float a = Rv[i2 * 5] * bb[m * 5];
                a = fmaf(Rv[i2 * 5 + 1], bb[m * 5 + 1], a);
                a = fmaf(Rv[i2 * 5 + 2], bb[m * 5 + 2], a);
                a = fmaf(Rv[i2 * 5 + 3], bb[m * 5 + 3], a);
                a = fmaf(Rv[i2 * 5 + 4], bb[m * 5 + 4], a);
                vv[u] = a;
            }
            float4 v; v.x = vv[0]; v.y = vv[1]; v.z = vv[2]; v.w = vv[3];
            *reinterpret_cast<float4*>(od + t4 * 4) = v;
        }
    }
}

extern "C" void kernel_launch(void* const* d_in, const int* in_sizes, int n_in,
                              void* d_out, int out_size)
{
    const float* feat  = (const float*)d_in[0];
    const float* basis = (const float*)d_in[1];
    const float* W1    = (const float*)d_in[2];
    const float* b1    = (const float*)d_in[3];
    const float* g1    = (const float*)d_in[4];
    const float* be1   = (const float*)d_in[5];
    const float* W2    = (const float*)d_in[6];
    const float* b2    = (const float*)d_in[7];
    const float* g2    = (const float*)d_in[8];
    const float* be2   = (const float*)d_in[9];
    const float* W3    = (const float*)d_in[10];
    const float* b3    = (const float*)d_in[11];
    float* out = (float*)d_out;

    cudaFuncSetAttribute(packW3_kernel,
                         cudaFuncAttributeMaxDynamicSharedMemorySize, PK_SMEM);
    cudaFuncSetAttribute(gemm_einsum_mma,
                         cudaFuncAttributeMaxDynamicSharedMemorySize, SMEM_TOTAL);

    packW3_kernel<<<NOBLK, 256, PK_SMEM>>>(W3);
    stage12_kernel<<<NROWS / RPB, 128>>>(feat, W1, b1, g1, be1, W2, b2, g2, be2);

    dim3 grid(NOBLK, MTILES);   // (32, 32)
    gemm_einsum_mma<<<grid, 512, SMEM_TOTAL>>>(b3, basis, out);
}

// round 12
// speedup vs baseline: 1.3084x; 1.0549x over previous
#include <cuda_runtime.h>
#include <cuda_bf16.h>
#include <cstdint>

// ---------------- problem constants ----------------
#define NROWS   4096
#define MID     128
#define OUTDIM  5120
#define BROW    125
#define LN_EPSF 1e-5f
#define RPB     8

#define MTILES  (NROWS / 128)    // 32 row tiles
#define NOBLK   32               // o blocks (160 cols each)

// ---- smem layout (bytes) for gemm kernel (CTA tile 128 x 80) ----
#define OFF_A_HI   0            // 32768  (128 x 128 bf16, swizzled)
#define OFF_A_LO   32768        // 32768
#define OFF_B_HI   65536        // 20480  (80 x 128 bf16, swizzled)
#define OFF_B_LO   86016        // 20480   -> operands end 106496
#define OFF_STG    0            // staging aliases A region: 128*85*4 = 43520
#define OFF_B3     106496       // 80 f32 = 320
#define SMEM_TOTAL 106816       // ~104.3 KB -> 2 CTAs/SM
#define SP         85           // staging pitch (floats), odd -> conflict-free LDS

// packW3 kernel smem: [128][161] f32
#define PK_PITCH   161
#define PK_SMEM    (128 * PK_PITCH * 4)   // 82432
// basT kernel smem: [128][126] f32
#define BT_PITCH   126
#define BT_SMEM    (128 * BT_PITCH * 4)   // 64512

// packed pre-swizzled operand images
__device__ __align__(16) __nv_bfloat16 g_Ahi[MTILES * 128 * 128];
__device__ __align__(16) __nv_bfloat16 g_Alo[MTILES * 128 * 128];
__device__ __align__(16) __nv_bfloat16 g_Bhi[NOBLK * 160 * 128];
__device__ __align__(16) __nv_bfloat16 g_Blo[NOBLK * 160 * 128];
// transposed basis: [rt][j 125][128 rows]
__device__ __align__(16) float g_basT[MTILES * BROW * 128];

// ---------------- helpers ----------------
__device__ __forceinline__ uint32_t smem_u32(const void* p) {
    uint32_t a;
    asm("{ .reg .u64 t; cvta.to.shared.u64 t, %1; cvt.u32.u64 %0, t; }" : "=r"(a) : "l"(p));
    return a;
}
__device__ __forceinline__ void cp_async16(uint32_t dst, const void* src) {
    asm volatile("cp.async.cg.shared.global [%0], [%1], 16;" :: "r"(dst), "l"(src));
}
__device__ __forceinline__ void cp_commit() { asm volatile("cp.async.commit_group;"); }
template <int N> __device__ __forceinline__ void cp_wait() {
    asm volatile("cp.async.wait_group %0;" :: "n"(N));
}

__device__ __forceinline__ void ldmx4(uint32_t* r, uint32_t addr) {
    asm volatile("ldmatrix.sync.aligned.m8n8.x4.shared.b16 {%0,%1,%2,%3}, [%4];"
                 : "=r"(r[0]), "=r"(r[1]), "=r"(r[2]), "=r"(r[3]) : "r"(addr));
}
__device__ __forceinline__ void mma16816(float* c, const uint32_t* a,
                                         uint32_t b0, uint32_t b1) {
    asm volatile(
        "mma.sync.aligned.m16n8k16.row.col.f32.bf16.bf16.f32 "
        "{%0,%1,%2,%3},{%4,%5,%6,%7},{%8,%9},{%0,%1,%2,%3};"
        : "+f"(c[0]), "+f"(c[1]), "+f"(c[2]), "+f"(c[3])
        : "r"(a[0]), "r"(a[1]), "r"(a[2]), "r"(a[3]), "r"(b0), "r"(b1));
}

// swizzled element index inside a [row][k=128] bf16 tile
__device__ __forceinline__ int swz_idx(int row, int k) {
    return row * 128 + ((((k >> 3) ^ (row & 7)) << 3) | (k & 7));
}

// =====================================================================
// stage12 kernel: LN/matvec/LN -> packed bf16 hi/lo A images
// =====================================================================
__global__ void __launch_bounds__(128) stage12_kernel(
    const float* __restrict__ feat,
    const float* __restrict__ W1, const float* __restrict__ b1,
    const float* __restrict__ g1, const float* __restrict__ be1,
    const float* __restrict__ W2, const float* __restrict__ b2,
    const float* __restrict__ g2, const float* __restrict__ be2)
{
    const int t = threadIdx.x;
    __shared__ float x1s[RPB][MID];
    __shared__ float redA[5][4];
    __shared__ float redB[RPB][2][4];

    const int warp = t >> 5, lane = t & 31;
    const int r0 = blockIdx.x * RPB;
    const float invM = 1.0f / (float)MID;

    const float w = W1[t], b = b1[t];
    float s0 = w, s1 = b, s2 = w * w, s3 = w * b, s4 = b * b;
    #pragma unroll
    for (int o = 16; o; o >>= 1) {
        s0 += __shfl_down_sync(0xffffffffu, s0, o);
        s1 += __shfl_down_sync(0xffffffffu, s1, o);
        s2 += __shfl_down_sync(0xffffffffu, s2, o);
        s3 += __shfl_down_sync(0xffffffffu, s3, o);
        s4 += __shfl_down_sync(0xffffffffu, s4, o);
    }
    if (!lane) {
        redA[0][warp] = s0; redA[1][warp] = s1; redA[2][warp] = s2;
        redA[3][warp] = s3; redA[4][warp] = s4;
    }
    __syncthreads();
    const float Sw  = redA[0][0] + redA[0][1] + redA[0][2] + redA[0][3];
    const float Sb  = redA[1][0] + redA[1][1] + redA[1][2] + redA[1][3];
    const float Sww = redA[2][0] + redA[2][1] + redA[2][2] + redA[2][3];
    const float Swb = redA[3][0] + redA[3][1] + redA[3][2] + redA[3][3];
    const float Sbb = redA[4][0] + redA[4][1] + redA[4][2] + redA[4][3];

    const float gg = g1[t], bg = be1[t];
    #pragma unroll
    for (int r = 0; r < RPB; r++) {
        float f   = feat[r0 + r];
        float mu  = (f * Sw + Sb) * invM;
        float e2  = (f * f * Sww + 2.0f * f * Swb + Sbb) * invM;
        float inv = rsqrtf(e2 - mu * mu + LN_EPSF);
        x1s[r][t] = fmaxf((f * w + b - mu) * inv * gg + bg, 0.0f);
    }
    __syncthreads();

    float acc[RPB];
    #pragma unroll
    for (int r = 0; r < RPB; r++) acc[r] = 0.0f;
    #pragma unroll 4
    for (int k = 0; k < MID; k++) {
        float wv = W2[k * MID + t];
        #pragma unroll
        for (int r = 0; r < RPB; r++) acc[r] = fmaf(x1s[r][k], wv, acc[r]);
    }
    const float bb2 = b2[t];
    #pragma unroll
    for (int r = 0; r < RPB; r++) acc[r] += bb2;

    #pragma unroll
    for (int r = 0; r < RPB; r++) {
        float v = acc[r], s = v, q = v * v;
        #pragma unroll
        for (int o = 16; o; o >>= 1) {
            s += __shfl_down_sync(0xffffffffu, s, o);
            q += __shfl_down_sync(0xffffffffu, q, o);
        }
        if (!lane) { redB[r][0][warp] = s; redB[r][1][warp] = q; }
    }
    __syncthreads();
    const float gv = g2[t], bv = be2[t];
    #pragma unroll
    for (int r = 0; r < RPB; r++) {
        float s  = redB[r][0][0] + redB[r][0][1] + redB[r][0][2] + redB[r][0][3];
        float q  = redB[r][1][0] + redB[r][1][1] + redB[r][1][2] + redB[r][1][3];
        float mu = s * invM;
        float inv = rsqrtf(q * invM - mu * mu + LN_EPSF);
        float v  = fmaxf((acc[r] - mu) * inv * gv + bv, 0.0f);
        int m = r0 + r;
        int tile = m >> 7, ml = m & 127;
        int idx = tile * 16384 + swz_idx(ml, t);
        __nv_bfloat16 h = __float2bfloat16(v);
        g_Ahi[idx] = h;
        g_Alo[idx] = __float2bfloat16(v - __bfloat162float(h));
    }
}

// =====================================================================
// packW3: per o-block, stage W3 chunk through smem (coalesced LDG),
// write swizzled hi/lo images with fully linear uint32 stores.
// =====================================================================
__global__ void __launch_bounds__(256) packW3_kernel(const float* __restrict__ W3)
{
    extern __shared__ float sw[];     // [128][PK_PITCH]
    const int o = blockIdx.x, t = threadIdx.x;

    for (int i = t; i < 128 * 160; i += 256) {
        int k = i / 160, n = i - k * 160;
        sw[k * PK_PITCH + n] = W3[(size_t)k * OUTDIM + o * 160 + n];
    }
    __syncthreads();

    uint32_t* bh = (uint32_t*)g_Bhi + o * 10240;
    uint32_t* bl = (uint32_t*)g_Blo + o * 10240;
    for (int i = t; i < 10240; i += 256) {
        int n = i >> 6, wq = i & 63;
        int q = 2 * wq;
        int k = (((q >> 3) ^ (n & 7)) << 3) | (q & 7);   // inverse swizzle
        float v0 = sw[k * PK_PITCH + n];
        float v1 = sw[(k + 1) * PK_PITCH + n];
        __nv_bfloat16 h0 = __float2bfloat16(v0), h1 = __float2bfloat16(v1);
        __nv_bfloat16 l0 = __float2bfloat16(v0 - __bfloat162float(h0));
        __nv_bfloat16 l1 = __float2bfloat16(v1 - __bfloat162float(h1));
        bh[i] = (uint32_t)__bfloat16_as_ushort(h0) |
                ((uint32_t)__bfloat16_as_ushort(h1) << 16);
        bl[i] = (uint32_t)__bfloat16_as_ushort(l0) |
                ((uint32_t)__bfloat16_as_ushort(l1) << 16);
    }
}

// =====================================================================
// basT: transpose basis rows into [rt][j 125][128 rows] for coalesced
// epilogue LDG (lane = row).
// =====================================================================
__global__ void __launch_bounds__(256) basT_kernel(const float* __restrict__ basis)
{
    extern __shared__ float sw[];     // [128][BT_PITCH]
    const int rt = blockIdx.x, t = threadIdx.x;

    for (int i = t; i < 128 * BROW; i += 256) {
        int r = i / BROW, j = i - r * BROW;
        sw[r * BT_PITCH + j] = basis[(size_t)(rt * 128 + r) * BROW + j];
    }
    __syncthreads();
    for (int i = t; i < BROW * 128; i += 256) {
        int j = i >> 7, r = i & 127;
        g_basT[((size_t)rt * BROW + j) * 128 + r] = sw[r * BT_PITCH + j];
    }
}

// =====================================================================
// GEMM (bf16x3 mma.sync, tile 128x80) + einsum epilogue.
// grid (64, 32): bx = ob*2 + h. 256 threads, 2 CTAs/SM.
// =====================================================================
__global__ void __launch_bounds__(256, 2)
gemm_einsum_mma(const float* __restrict__ b3,
                float* __restrict__ out)
{
    extern __shared__ __align__(16) char smem[];
    const uint32_t sb = smem_u32(smem);
    const int tid  = threadIdx.x;
    const int wid  = tid >> 5, lane = tid & 31;
    const int ob   = blockIdx.x >> 1;     // o block (0..31)
    const int h    = blockIdx.x & 1;      // column half (80 cols)
    const int rt   = blockIdx.y;          // row tile (0..31)
    const int r0   = rt * 128;

    // ---- cp.async: A hi/lo (64KB), B half hi/lo (40KB), b3 slice
    {
        const char* sAh = (const char*)(g_Ahi + (size_t)rt * 16384);
        const char* sAl = (const char*)(g_Alo + (size_t)rt * 16384);
        const char* sBh = (const char*)(g_Bhi + (size_t)ob * 20480 + h * 10240);
        const char* sBl = (const char*)(g_Blo + (size_t)ob * 20480 + h * 10240);
        for (int i = tid; i < 2048; i += 256) {
            cp_async16(sb + OFF_A_HI + i * 16, sAh + i * 16);
            cp_async16(sb + OFF_A_LO + i * 16, sAl + i * 16);
        }
        for (int i = tid; i < 1280; i += 256) {
            cp_async16(sb + OFF_B_HI + i * 16, sBh + i * 16);
            cp_async16(sb + OFF_B_LO + i * 16, sBl + i * 16);
        }
        const char* b3p = (const char*)(b3 + ob * 160 + h * 80);
        if (tid < 20) cp_async16(sb + OFF_B3 + tid * 16, b3p + tid * 16);
        cp_commit();
    }
    cp_wait<0>();
    __syncthreads();

    // ---- MMA mainloop: warp mg = wid (16 rows), full 80 B-rows/warp ----
    const int mg = wid;                   // mtile 0..7
    const int axor = lane & 7;
    const int ak   = lane >> 4;
    const int bk   = (lane >> 3) & 1;

    const uint32_t aAddr = sb + OFF_A_HI + ((mg * 16 + (lane & 15)) << 8);
    const uint32_t bAddr0 = sb + OFF_B_HI +
        ((((lane >> 4) & 1) * 8 + (lane & 7)) << 8);

    float c[10][4];
    #pragma unroll
    for (int n = 0; n < 10; n++)
        #pragma unroll
        for (int q = 0; q < 4; q++) c[n][q] = 0.0f;

    #pragma unroll
    for (int kk = 0; kk < 8; kk++) {
        uint32_t gA = (uint32_t)(((2 * kk + ak) ^ axor) << 4);
        uint32_t gB = (uint32_t)(((2 * kk + bk) ^ axor) << 4);
        uint32_t ah[4], al[4];
        ldmx4(ah, aAddr + gA);
        ldmx4(al, aAddr + 32768 + gA);
        #pragma unroll
        for (int j2 = 0; j2 < 5; j2++) {
            uint32_t bh[4], bl[4];
            uint32_t ba = bAddr0 + j2 * 4096 + gB;
            ldmx4(bh, ba);
            ldmx4(bl, ba + 20480);
            mma16816(c[2 * j2], ah, bh[0], bh[1]);
            mma16816(c[2 * j2], ah, bl[0], bl[1]);
            mma16816(c[2 * j2], al, bh[0], bh[1]);
            mma16816(c[2 * j2 + 1], ah, bh[2], bh[3]);
            mma16816(c[2 * j2 + 1], ah, bl[2], bl[3]);
            mma16816(c[2 * j2 + 1], al, bh[2], bh[3]);
        }
    }

    __syncthreads();   // operands dead; staging may overwrite A region

    // ---- stage C to smem [128][SP]
    float* stg = (float*)(smem + OFF_STG);
    {
        const int rlo = mg * 16 + (lane >> 2);
        const int rhi = rlo + 8;
        #pragma unroll
        for (int ntl = 0; ntl < 10; ntl++) {
            int col = ntl * 8 + 2 * (lane & 3);
            stg[rlo * SP + col]     = c[ntl][0];
            stg[rlo * SP + col + 1] = c[ntl][1];
            stg[rhi * SP + col]     = c[ntl][2];
            stg[rhi * SP + col + 1] = c[ntl][3];
        }
    }
    __syncthreads();

    // ---- einsum epilogue: warp = (rowgroup rg 0..3, i-half ih 0..1)
    const int rg    = wid >> 1;
    const int ih    = wid & 1;
    const int rloc  = rg * 32 + lane;
    const float* sB3 = (const float*)(smem + OFF_B3) + ih * 40;
    const float* Rp  = stg + rloc * SP + ih * 40;
    const float* BTg = g_basT + (size_t)rt * BROW * 128 + rg * 32 + lane;

    float Rv[40];
    #pragma unroll
    for (int t2 = 0; t2 < 40; t2++) Rv[t2] = Rp[t2] + sB3[t2];

    float* obase = out + (size_t)(r0 + rloc) * 25600 + (size_t)ob * 800 +
                   h * 80 + ih * 40;
    #pragma unroll 1
    for (int d = 0; d < 5; d++) {
        float bb[25];
        #pragma unroll
        for (int q = 0; q < 25; q++) bb[q] = BTg[(d * 25 + q) * 128];
        float* od = obase + d * 160;
        #pragma unroll
        for (int t4 = 0; t4 < 10; t4++) {
            float vv[4];
            #pragma unroll
            for (int u = 0; u < 4; u++) {
                int t2 = t4 * 4 + u;
                int i2 = t2 / 5, m = t2 % 5;
                float a = Rv[i2 * 5] * bb[m * 5];
                a = fmaf(Rv[i2 * 5 + 1], bb[m * 5 + 1], a);
                a = fmaf(Rv[i2 * 5 + 2], bb[m * 5 + 2], a);
                a = fmaf(Rv[i2 * 5 + 3], bb[m * 5 + 3], a);
                a = fmaf(Rv[i2 * 5 + 4], bb[m * 5 + 4], a);
                vv[u] = a;
            }
            float4 v; v.x = vv[0]; v.y = vv[1]; v.z = vv[2]; v.w = vv[3];
            *reinterpret_cast<float4*>(od + t4 * 4) = v;
        }
    }
}

extern "C" void kernel_launch(void* const* d_in, const int* in_sizes, int n_in,
                              void* d_out, int out_size)
{
    const float* feat  = (const float*)d_in[0];
    const float* basis = (const float*)d_in[1];
    const float* W1    = (const float*)d_in[2];
    const float* b1    = (const float*)d_in[3];
    const float* g1    = (const float*)d_in[4];
    const float* be1   = (const float*)d_in[5];
    const float* W2    = (const float*)d_in[6];
    const float* b2    = (const float*)d_in[7];
    const float* g2    = (const float*)d_in[8];
    const float* be2   = (const float*)d_in[9];
    const float* W3    = (const float*)d_in[10];
    const float* b3    = (const float*)d_in[11];
    float* out = (float*)d_out;

    cudaFuncSetAttribute(packW3_kernel,
                         cudaFuncAttributeMaxDynamicSharedMemorySize, PK_SMEM);
    cudaFuncSetAttribute(basT_kernel,
                         cudaFuncAttributeMaxDynamicSharedMemorySize, BT_SMEM);
    cudaFuncSetAttribute(gemm_einsum_mma,
                         cudaFuncAttributeMaxDynamicSharedMemorySize, SMEM_TOTAL);

    packW3_kernel<<<NOBLK, 256, PK_SMEM>>>(W3);
    basT_kernel<<<MTILES, 256, BT_SMEM>>>(basis);
    stage12_kernel<<<NROWS / RPB, 128>>>(feat, W1, b1, g1, be1, W2, b2, g2, be2);

    dim3 grid(NOBLK * 2, MTILES);   // (64, 32)
    gemm_einsum_mma<<<grid, 256, SMEM_TOTAL>>>(b3, out);
}

// round 13
// speedup vs baseline: 1.6785x; 1.2829x over previous
#include <cuda_runtime.h>
#include <cuda_bf16.h>
#include <cstdint>

// ---------------- problem constants ----------------
#define NROWS   4096
#define MID     128
#define OUTDIM  5120
#define BROW    125
#define LN_EPSF 1e-5f
#define RPB     8

#define MTILES  (NROWS / 128)    // 32 row tiles
#define NOBLK   32               // o blocks (160 cols each)

// ---- smem layout (bytes) for gemm kernel (CTA tile 128 x 80) ----
#define OFF_A_HI   0            // 32768  (128 x 128 bf16, swizzled)
#define OFF_A_LO   32768        // 32768
#define OFF_B_HI   65536        // 20480  (80 x 128 bf16, swizzled)
#define OFF_B_LO   86016        // 20480   -> operands end 106496
// post-mainloop reuse:
#define OFF_STGC   0            // C staging: 128 x 81 f32 = 41472
#define OFF_BASS   41472        // basis tile: 128 x 128 f32 = 65536 (ends 107008)
#define OFF_B3     107008       // 80 f32 = 320 (fresh space, no alias)
#define SMEM_TOTAL 107328       // ~104.8 KB -> 2 CTAs/SM
#define SPC        81           // C staging pitch (odd -> conflict-free)

// packW3 kernel smem: [128][161] f32
#define PK_PITCH   161
#define PK_SMEM    (128 * PK_PITCH * 4)   // 82432

// packed pre-swizzled operand images
__device__ __align__(16) __nv_bfloat16 g_Ahi[MTILES * 128 * 128];
__device__ __align__(16) __nv_bfloat16 g_Alo[MTILES * 128 * 128];
__device__ __align__(16) __nv_bfloat16 g_Bhi[NOBLK * 160 * 128];
__device__ __align__(16) __nv_bfloat16 g_Blo[NOBLK * 160 * 128];
// padded basis image: [rt][128 rows][128 j] (125 used)
__device__ __align__(16) float g_basP[MTILES * 128 * 128];

// ---------------- helpers ----------------
__device__ __forceinline__ uint32_t smem_u32(const void* p) {
    uint32_t a;
    asm("{ .reg .u64 t; cvta.to.shared.u64 t, %1; cvt.u32.u64 %0, t; }" : "=r"(a) : "l"(p));
    return a;
}
__device__ __forceinline__ void cp_async16(uint32_t dst, const void* src) {
    asm volatile("cp.async.cg.shared.global [%0], [%1], 16;" :: "r"(dst), "l"(src));
}
__device__ __forceinline__ void cp_commit() { asm volatile("cp.async.commit_group;"); }
template <int N> __device__ __forceinline__ void cp_wait() {
    asm volatile("cp.async.wait_group %0;" :: "n"(N));
}

__device__ __forceinline__ void ldmx4(uint32_t* r, uint32_t addr) {
    asm volatile("ldmatrix.sync.aligned.m8n8.x4.shared.b16 {%0,%1,%2,%3}, [%4];"
                 : "=r"(r[0]), "=r"(r[1]), "=r"(r[2]), "=r"(r[3]) : "r"(addr));
}
__device__ __forceinline__ void mma16816(float* c, const uint32_t* a,
                                         uint32_t b0, uint32_t b1) {
    asm volatile(
        "mma.sync.aligned.m16n8k16.row.col.f32.bf16.bf16.f32 "
        "{%0,%1,%2,%3},{%4,%5,%6,%7},{%8,%9},{%0,%1,%2,%3};"
        : "+f"(c[0]), "+f"(c[1]), "+f"(c[2]), "+f"(c[3])
        : "r"(a[0]), "r"(a[1]), "r"(a[2]), "r"(a[3]), "r"(b0), "r"(b1));
}

// swizzled element index inside a [row][k=128] bf16 tile
__device__ __forceinline__ int swz_idx(int row, int k) {
    return row * 128 + ((((k >> 3) ^ (row & 7)) << 3) | (k & 7));
}

// =====================================================================
// stage12 kernel: LN/matvec/LN -> packed bf16 hi/lo A images
// =====================================================================
__global__ void __launch_bounds__(128) stage12_kernel(
    const float* __restrict__ feat,
    const float* __restrict__ W1, const float* __restrict__ b1,
    const float* __restrict__ g1, const float* __restrict__ be1,
    const float* __restrict__ W2, const float* __restrict__ b2,
    const float* __restrict__ g2, const float* __restrict__ be2)
{
    const int t = threadIdx.x;
    __shared__ float x1s[RPB][MID];
    __shared__ float redA[5][4];
    __shared__ float redB[RPB][2][4];

    const int warp = t >> 5, lane = t & 31;
    const int r0 = blockIdx.x * RPB;
    const float invM = 1.0f / (float)MID;

    const float w = W1[t], b = b1[t];
    float s0 = w, s1 = b, s2 = w * w, s3 = w * b, s4 = b * b;
    #pragma unroll
    for (int o = 16; o; o >>= 1) {
        s0 += __shfl_down_sync(0xffffffffu, s0, o);
        s1 += __shfl_down_sync(0xffffffffu, s1, o);
        s2 += __shfl_down_sync(0xffffffffu, s2, o);
        s3 += __shfl_down_sync(0xffffffffu, s3, o);
        s4 += __shfl_down_sync(0xffffffffu, s4, o);
    }
    if (!lane) {
        redA[0][warp] = s0; redA[1][warp] = s1; redA[2][warp] = s2;
        redA[3][warp] = s3; redA[4][warp] = s4;
    }
    __syncthreads();
    const float Sw  = redA[0][0] + redA[0][1] + redA[0][2] + redA[0][3];
    const float Sb  = redA[1][0] + redA[1][1] + redA[1][2] + redA[1][3];
    const float Sww = redA[2][0] + redA[2][1] + redA[2][2] + redA[2][3];
    const float Swb = redA[3][0] + redA[3][1] + redA[3][2] + redA[3][3];
    const float Sbb = redA[4][0] + redA[4][1] + redA[4][2] + redA[4][3];

    const float gg = g1[t], bg = be1[t];
    #pragma unroll
    for (int r = 0; r < RPB; r++) {
        float f   = feat[r0 + r];
        float mu  = (f * Sw + Sb) * invM;
        float e2  = (f * f * Sww + 2.0f * f * Swb + Sbb) * invM;
        float inv = rsqrtf(e2 - mu * mu + LN_EPSF);
        x1s[r][t] = fmaxf((f * w + b - mu) * inv * gg + bg, 0.0f);
    }
    __syncthreads();

    float acc[RPB];
    #pragma unroll
    for (int r = 0; r < RPB; r++) acc[r] = 0.0f;
    #pragma unroll 4
    for (int k = 0; k < MID; k++) {
        float wv = W2[k * MID + t];
        #pragma unroll
        for (int r = 0; r < RPB; r++) acc[r] = fmaf(x1s[r][k], wv, acc[r]);
    }
    const float bb2 = b2[t];
    #pragma unroll
    for (int r = 0; r < RPB; r++) acc[r] += bb2;

    #pragma unroll
    for (int r = 0; r < RPB; r++) {
        float v = acc[r], s = v, q = v * v;
        #pragma unroll
        for (int o = 16; o; o >>= 1) {
            s += __shfl_down_sync(0xffffffffu, s, o);
            q += __shfl_down_sync(0xffffffffu, q, o);
        }
        if (!lane) { redB[r][0][warp] = s; redB[r][1][warp] = q; }
    }
    __syncthreads();
    const float gv = g2[t], bv = be2[t];
    #pragma unroll
    for (int r = 0; r < RPB; r++) {
        float s  = redB[r][0][0] + redB[r][0][1] + redB[r][0][2] + redB[r][0][3];
        float q  = redB[r][1][0] + redB[r][1][1] + redB[r][1][2] + redB[r][1][3];
        float mu = s * invM;
        float inv = rsqrtf(q * invM - mu * mu + LN_EPSF);
        float v  = fmaxf((acc[r] - mu) * inv * gv + bv, 0.0f);
        int m = r0 + r;
        int tile = m >> 7, ml = m & 127;
        int idx = tile * 16384 + swz_idx(ml, t);
        __nv_bfloat16 h = __float2bfloat16(v);
        g_Ahi[idx] = h;
        g_Alo[idx] = __float2bfloat16(v - __bfloat162float(h));
    }
}

// =====================================================================
// packW3: per o-block, stage W3 chunk through smem (coalesced LDG),
// write swizzled hi/lo images with fully linear uint32 stores.
// =====================================================================
__global__ void __launch_bounds__(256) packW3_kernel(const float* __restrict__ W3)
{
    extern __shared__ float sw[];     // [128][PK_PITCH]
    const int o = blockIdx.x, t = threadIdx.x;

    for (int i = t; i < 128 * 160; i += 256) {
        int k = i / 160, n = i - k * 160;
        sw[k * PK_PITCH + n] = W3[(size_t)k * OUTDIM + o * 160 + n];
    }
    __syncthreads();

    uint32_t* bh = (uint32_t*)g_Bhi + o * 10240;
    uint32_t* bl = (uint32_t*)g_Blo + o * 10240;
    for (int i = t; i < 10240; i += 256) {
        int n = i >> 6, wq = i & 63;
        int q = 2 * wq;
        int k = (((q >> 3) ^ (n & 7)) << 3) | (q & 7);   // inverse swizzle
        float v0 = sw[k * PK_PITCH + n];
        float v1 = sw[(k + 1) * PK_PITCH + n];
        __nv_bfloat16 h0 = __float2bfloat16(v0), h1 = __float2bfloat16(v1);
        __nv_bfloat16 l0 = __float2bfloat16(v0 - __bfloat162float(h0));
        __nv_bfloat16 l1 = __float2bfloat16(v1 - __bfloat162float(h1));
        bh[i] = (uint32_t)__bfloat16_as_ushort(h0) |
                ((uint32_t)__bfloat16_as_ushort(h1) << 16);
        bl[i] = (uint32_t)__bfloat16_as_ushort(l0) |
                ((uint32_t)__bfloat16_as_ushort(l1) << 16);
    }
}

// =====================================================================
// basP: pad basis rows to pitch 128 ([rt][128 rows][128 j], 125 used)
// so the gemm kernel can cp.async it (16B-aligned rows).
// =====================================================================
__global__ void __launch_bounds__(256) basP_kernel(const float* __restrict__ basis)
{
    const int rt = blockIdx.x, t = threadIdx.x;
    float* dst = g_basP + (size_t)rt * 16384;
    const float* src = basis + (size_t)rt * 128 * BROW;
    for (int i = t; i < 128 * BROW; i += 256) {
        int r = i / BROW, j = i - r * BROW;
        dst[r * 128 + j] = src[i];
    }
}

// =====================================================================
// GEMM (bf16x3 mma.sync, tile 128x80) + warp-per-row einsum epilogue.
// grid (64, 32): bx = ob*2 + h. 256 threads, 2 CTAs/SM.
// =====================================================================
__global__ void __launch_bounds__(256, 2)
gemm_einsum_mma(const float* __restrict__ b3,
                float* __restrict__ out)
{
    extern __shared__ __align__(16) char smem[];
    const uint32_t sb = smem_u32(smem);
    const int tid  = threadIdx.x;
    const int wid  = tid >> 5, lane = tid & 31;
    const int ob   = blockIdx.x >> 1;     // o block (0..31)
    const int h    = blockIdx.x & 1;      // column half (80 cols)
    const int rt   = blockIdx.y;          // row tile (0..31)
    const int r0   = rt * 128;

    // ---- cp.async: A hi/lo (64KB), B half hi/lo (40KB), b3 slice
    {
        const char* sAh = (const char*)(g_Ahi + (size_t)rt * 16384);
        const char* sAl = (const char*)(g_Alo + (size_t)rt * 16384);
        const char* sBh = (const char*)(g_Bhi + (size_t)ob * 20480 + h * 10240);
        const char* sBl = (const char*)(g_Blo + (size_t)ob * 20480 + h * 10240);
        for (int i = tid; i < 2048; i += 256) {
            cp_async16(sb + OFF_A_HI + i * 16, sAh + i * 16);
            cp_async16(sb + OFF_A_LO + i * 16, sAl + i * 16);
        }
        for (int i = tid; i < 1280; i += 256) {
            cp_async16(sb + OFF_B_HI + i * 16, sBh + i * 16);
            cp_async16(sb + OFF_B_LO + i * 16, sBl + i * 16);
        }
        const char* b3p = (const char*)(b3 + ob * 160 + h * 80);
        if (tid < 20) cp_async16(sb + OFF_B3 + tid * 16, b3p + tid * 16);
        cp_commit();
    }
    cp_wait<0>();
    __syncthreads();

    // ---- MMA mainloop: warp mg = wid (16 rows), full 80 B-rows/warp ----
    const int mg = wid;                   // mtile 0..7
    const int axor = lane & 7;
    const int ak   = lane >> 4;
    const int bk   = (lane >> 3) & 1;

    const uint32_t aAddr = sb + OFF_A_HI + ((mg * 16 + (lane & 15)) << 8);
    const uint32_t bAddr0 = sb + OFF_B_HI +
        ((((lane >> 4) & 1) * 8 + (lane & 7)) << 8);

    float c[10][4];
    #pragma unroll
    for (int n = 0; n < 10; n++)
        #pragma unroll
        for (int q = 0; q < 4; q++) c[n][q] = 0.0f;

    #pragma unroll
    for (int kk = 0; kk < 8; kk++) {
        uint32_t gA = (uint32_t)(((2 * kk + ak) ^ axor) << 4);
        uint32_t gB = (uint32_t)(((2 * kk + bk) ^ axor) << 4);
        uint32_t ah[4], al[4];
        ldmx4(ah, aAddr + gA);
        ldmx4(al, aAddr + 32768 + gA);
        #pragma unroll
        for (int j2 = 0; j2 < 5; j2++) {
            uint32_t bh[4], bl[4];
            uint32_t ba = bAddr0 + j2 * 4096 + gB;
            ldmx4(bh, ba);
            ldmx4(bl, ba + 20480);
            mma16816(c[2 * j2], ah, bh[0], bh[1]);
            mma16816(c[2 * j2], ah, bl[0], bl[1]);
            mma16816(c[2 * j2], al, bh[0], bh[1]);
            mma16816(c[2 * j2 + 1], ah, bh[2], bh[3]);
            mma16816(c[2 * j2 + 1], ah, bl[2], bl[3]);
            mma16816(c[2 * j2 + 1], al, bh[2], bh[3]);
        }
    }

    __syncthreads();   // all operand reads done; smem reusable

    // ---- kick basis cp.async into dead operand region (overlaps staging)
    {
        const char* bas = (const char*)(g_basP + (size_t)rt * 16384);
        for (int i = tid; i < 4096; i += 256)
            cp_async16(sb + OFF_BASS + i * 16, bas + i * 16);
        cp_commit();
    }

    // ---- stage C (+b3) to smem [128][SPC]
    float* stg = (float*)(smem + OFF_STGC);
    const float* sB3 = (const float*)(smem + OFF_B3);
    {
        const int rlo = mg * 16 + (lane >> 2);
        const int rhi = rlo + 8;
        #pragma unroll
        for (int ntl = 0; ntl < 10; ntl++) {
            int col = ntl * 8 + 2 * (lane & 3);
            float bA = sB3[col], bB = sB3[col + 1];
            stg[rlo * SPC + col]     = c[ntl][0] + bA;
            stg[rlo * SPC + col + 1] = c[ntl][1] + bB;
            stg[rhi * SPC + col]     = c[ntl][2] + bA;
            stg[rhi * SPC + col + 1] = c[ntl][3] + bB;
        }
    }
    cp_wait<0>();        // basis landed
    __syncthreads();

    // ---- warp-per-row einsum epilogue: warp wid owns rows wid*16..+15.
    // Lanes sweep output columns in 3 passes (32,32,16) -> coalesced STG.
    const float* bass = (const float*)(smem + OFF_BASS);

    int colp[3], ip[3], mp[3];
    #pragma unroll
    for (int p = 0; p < 3; p++) {
        colp[p] = p * 32 + lane;
        ip[p]   = colp[p] / 5;
        mp[p]   = colp[p] - 5 * ip[p];
    }
    const int blane = (lane < 25) ? lane : 0;

    #pragma unroll 1
    for (int rr = 0; rr < 16; rr++) {
        const int rloc = wid * 16 + rr;
        const float* Rrow = stg + rloc * SPC;
        float Rf[3][5];
        #pragma unroll
        for (int p = 0; p < 3; p++)
            #pragma unroll
            for (int f = 0; f < 5; f++)
                Rf[p][f] = Rrow[ip[p] * 5 + f];

        const float* basRow = bass + rloc * 128;
        float* outR = out + (size_t)(r0 + rloc) * 25600 + (size_t)ob * 800 + h * 80;

        #pragma unroll
        for (int d = 0; d < 5; d++) {
            float bval = basRow[d * 25 + blane];   // lane q holds bas[d*25+q]
            #pragma unroll
            for (int p = 0; p < 3; p++) {
                float a = 0.0f;
                #pragma unroll
                for (int f = 0; f < 5; f++) {
                    float bf = __shfl_sync(0xffffffffu, bval, mp[p] * 5 + f);
                    a = fmaf(Rf[p][f], bf, a);
                }
                if (p < 2 || lane < 16)
                    outR[d * 160 + colp[p]] = a;
            }
        }
    }
}

extern "C" void kernel_launch(void* const* d_in, const int* in_sizes, int n_in,
                              void* d_out, int out_size)
{
    const float* feat  = (const float*)d_in[0];
    const float* basis = (const float*)d_in[1];
    const float* W1    = (const float*)d_in[2];
    const float* b1    = (const float*)d_in[3];
    const float* g1    = (const float*)d_in[4];
    const float* be1   = (const float*)d_in[5];
    const float* W2    = (const float*)d_in[6];
    const float* b2    = (const float*)d_in[7];
    const float* g2    = (const float*)d_in[8];
    const float* be2   = (const float*)d_in[9];
    const float* W3    = (const float*)d_in[10];
    const float* b3    = (const float*)d_in[11];
    float* out = (float*)d_out;

    cudaFuncSetAttribute(packW3_kernel,
                         cudaFuncAttributeMaxDynamicSharedMemorySize, PK_SMEM);
    cudaFuncSetAttribute(gemm_einsum_mma,
                         cudaFuncAttributeMaxDynamicSharedMemorySize, SMEM_TOTAL);

    packW3_kernel<<<NOBLK, 256, PK_SMEM>>>(W3);
    basP_kernel<<<MTILES, 256>>>(basis);
    stage12_kernel<<<NROWS / RPB, 128>>>(feat, W1, b1, g1, be1, W2, b2, g2, be2);

    dim3 grid(NOBLK * 2, MTILES);   // (64, 32)
    gemm_einsum_mma<<<grid, 256, SMEM_TOTAL>>>(b3, out);
}

// round 14
// speedup vs baseline: 1.9403x; 1.1560x over previous
#include <cuda_runtime.h>
#include <cuda_bf16.h>
#include <cstdint>

// ---------------- problem constants ----------------
#define NROWS   4096
#define MID     128
#define OUTDIM  5120
#define BROW    125
#define LN_EPSF 1e-5f

#define MTILES  (NROWS / 128)    // 32 row tiles
#define NOBLK   32               // o blocks (160 cols each)

// ---- smem layout (bytes) for gemm kernel (CTA tile 128 x 80) ----
#define OFF_A_HI   0            // 32768  (128 x 128 bf16, swizzled)
#define OFF_A_LO   32768        // 32768
#define OFF_B_HI   65536        // 20480  (80 x 128 bf16, swizzled)
#define OFF_B_LO   86016        // 20480   -> operands end 106496
#define OFF_STGC   0            // C staging aliases operands: 128*81*4 = 41472
#define OFF_B3     106496       // 80 f32 = 320
#define SMEM_TOTAL 106816       // ~104.3 KB -> 2 CTAs/SM
#define SPC        81           // C staging pitch (odd -> conflict-free)

// packed pre-swizzled operand images
__device__ __align__(16) __nv_bfloat16 g_Ahi[MTILES * 128 * 128];
__device__ __align__(16) __nv_bfloat16 g_Alo[MTILES * 128 * 128];
__device__ __align__(16) __nv_bfloat16 g_Bhi[NOBLK * 160 * 128];
__device__ __align__(16) __nv_bfloat16 g_Blo[NOBLK * 160 * 128];
// padded basis image: [rt][128 rows][128 j] (125 used)
__device__ __align__(16) float g_basP[MTILES * 128 * 128];

// ---------------- helpers ----------------
__device__ __forceinline__ uint32_t smem_u32(const void* p) {
    uint32_t a;
    asm("{ .reg .u64 t; cvta.to.shared.u64 t, %1; cvt.u32.u64 %0, t; }" : "=r"(a) : "l"(p));
    return a;
}
__device__ __forceinline__ void cp_async16(uint32_t dst, const void* src) {
    asm volatile("cp.async.cg.shared.global [%0], [%1], 16;" :: "r"(dst), "l"(src));
}
__device__ __forceinline__ void cp_commit() { asm volatile("cp.async.commit_group;"); }
template <int N> __device__ __forceinline__ void cp_wait() {
    asm volatile("cp.async.wait_group %0;" :: "n"(N));
}
__device__ __forceinline__ void ldmx4(uint32_t* r, uint32_t addr) {
    asm volatile("ldmatrix.sync.aligned.m8n8.x4.shared.b16 {%0,%1,%2,%3}, [%4];"
                 : "=r"(r[0]), "=r"(r[1]), "=r"(r[2]), "=r"(r[3]) : "r"(addr));
}
__device__ __forceinline__ void ldmx2(uint32_t* r, uint32_t addr) {
    asm volatile("ldmatrix.sync.aligned.m8n8.x2.shared.b16 {%0,%1}, [%2];"
                 : "=r"(r[0]), "=r"(r[1]) : "r"(addr));
}
__device__ __forceinline__ void mma16816(float* c, const uint32_t* a,
                                         uint32_t b0, uint32_t b1) {
    asm volatile(
        "mma.sync.aligned.m16n8k16.row.col.f32.bf16.bf16.f32 "
        "{%0,%1,%2,%3},{%4,%5,%6,%7},{%8,%9},{%0,%1,%2,%3};"
        : "+f"(c[0]), "+f"(c[1]), "+f"(c[2]), "+f"(c[3])
        : "r"(a[0]), "r"(a[1]), "r"(a[2]), "r"(a[3]), "r"(b0), "r"(b1));
}
// swizzled element index inside a [row][k=128] bf16 tile
__device__ __forceinline__ int swz_idx(int row, int k) {
    return row * 128 + ((((k >> 3) ^ (row & 7)) << 3) | (k & 7));
}

// =====================================================================
// Fused prep kernel, grid 416 x 256 threads:
//  [0,128)   packW3: (o = b>>2, nq = b&3) -> B hi/lo images
//  [128,160) basP:   pad basis to pitch-128 image
//  [160,416) stage12: 16 rows each (two 128-thread subgroups) -> A images
// =====================================================================
__global__ void __launch_bounds__(256) prep_kernel(
    const float* __restrict__ feat,  const float* __restrict__ basis,
    const float* __restrict__ W1, const float* __restrict__ b1,
    const float* __restrict__ g1, const float* __restrict__ be1,
    const float* __restrict__ W2, const float* __restrict__ b2,
    const float* __restrict__ g2, const float* __restrict__ be2,
    const float* __restrict__ W3)
{
    __shared__ __align__(16) char shraw[22528];
    const int b = blockIdx.x, t = threadIdx.x;

    if (b < 128) {
        // ---- packW3: o-block, n-quarter (40 cols) ----
        float* sw = (float*)shraw;                 // [128][41]
        const int o = b >> 2, nq = b & 3;
        for (int i = t; i < 128 * 40; i += 256) {
            int k = i / 40, nl = i - k * 40;
            sw[k * 41 + nl] = W3[(size_t)k * OUTDIM + o * 160 + nq * 40 + nl];
        }
        __syncthreads();
        uint32_t* bh = (uint32_t*)g_Bhi + o * 10240 + nq * 2560;
        uint32_t* bl = (uint32_t*)g_Blo + o * 10240 + nq * 2560;
        for (int li = t; li < 2560; li += 256) {
            int nl = li >> 6, wq = li & 63;
            int q = 2 * wq;
            int k = (((q >> 3) ^ (nl & 7)) << 3) | (q & 7);   // inverse swizzle
            float v0 = sw[k * 41 + nl];
            float v1 = sw[(k + 1) * 41 + nl];
            __nv_bfloat16 h0 = __float2bfloat16(v0), h1 = __float2bfloat16(v1);
            __nv_bfloat16 l0 = __float2bfloat16(v0 - __bfloat162float(h0));
            __nv_bfloat16 l1 = __float2bfloat16(v1 - __bfloat162float(h1));
            bh[li] = (uint32_t)__bfloat16_as_ushort(h0) |
                     ((uint32_t)__bfloat16_as_ushort(h1) << 16);
            bl[li] = (uint32_t)__bfloat16_as_ushort(l0) |
                     ((uint32_t)__bfloat16_as_ushort(l1) << 16);
        }
        return;
    }
    if (b < 160) {
        // ---- basP ----
        const int rt = b - 128;
        float* dst = g_basP + (size_t)rt * 16384;
        const float* src = basis + (size_t)rt * 128 * BROW;
        for (int i = t; i < 128 * BROW; i += 256) {
            int r = i / BROW, j = i - r * BROW;
            dst[r * 128 + j] = src[i];
        }
        return;
    }

    // ---- stage12 ----
    float* xs = (float*)shraw;                     // [2][8][128]
    float* rA = (float*)(shraw + 8192);            // [2][5][4]
    float* rB = (float*)(shraw + 8192 + 256);      // [2][8][2][4]
    const int b2i = b - 160;
    const int g  = t >> 7, tl = t & 127;
    const int w4 = tl >> 5, lane = t & 31;
    const int r0 = b2i * 16 + g * 8;
    const float invM = 1.0f / (float)MID;

    const float w = W1[tl], bb = b1[tl];
    float s0 = w, s1 = bb, s2 = w * w, s3 = w * bb, s4 = bb * bb;
    #pragma unroll
    for (int o = 16; o; o >>= 1) {
        s0 += __shfl_down_sync(0xffffffffu, s0, o);
        s1 += __shfl_down_sync(0xffffffffu, s1, o);
        s2 += __shfl_down_sync(0xffffffffu, s2, o);
        s3 += __shfl_down_sync(0xffffffffu, s3, o);
        s4 += __shfl_down_sync(0xffffffffu, s4, o);
    }
    if (!lane) {
        rA[(g * 5 + 0) * 4 + w4] = s0; rA[(g * 5 + 1) * 4 + w4] = s1;
        rA[(g * 5 + 2) * 4 + w4] = s2; rA[(g * 5 + 3) * 4 + w4] = s3;
        rA[(g * 5 + 4) * 4 + w4] = s4;
    }
    __syncthreads();
    float S[5];
    #pragma unroll
    for (int j = 0; j < 5; j++)
        S[j] = rA[(g * 5 + j) * 4 + 0] + rA[(g * 5 + j) * 4 + 1] +
               rA[(g * 5 + j) * 4 + 2] + rA[(g * 5 + j) * 4 + 3];

    const float gg = g1[tl], bg = be1[tl];
    #pragma unroll
    for (int r = 0; r < 8; r++) {
        float f   = feat[r0 + r];
        float mu  = (f * S[0] + S[1]) * invM;
        float e2  = (f * f * S[2] + 2.0f * f * S[3] + S[4]) * invM;
        float inv = rsqrtf(e2 - mu * mu + LN_EPSF);
        xs[(g * 8 + r) * 128 + tl] = fmaxf((f * w + bb - mu) * inv * gg + bg, 0.0f);
    }
    __syncthreads();

    float acc[8];
    #pragma unroll
    for (int r = 0; r < 8; r++) acc[r] = 0.0f;
    #pragma unroll 4
    for (int k = 0; k < MID; k++) {
        float wv = W2[k * MID + tl];
        #pragma unroll
        for (int r = 0; r < 8; r++) acc[r] = fmaf(xs[(g * 8 + r) * 128 + k], wv, acc[r]);
    }
    const float bv2 = b2[tl];
    #pragma unroll
    for (int r = 0; r < 8; r++) acc[r] += bv2;

    #pragma unroll
    for (int r = 0; r < 8; r++) {
        float v = acc[r], s = v, q = v * v;
        #pragma unroll
        for (int o = 16; o; o >>= 1) {
            s += __shfl_down_sync(0xffffffffu, s, o);
            q += __shfl_down_sync(0xffffffffu, q, o);
        }
        if (!lane) {
            rB[((g * 8 + r) * 2 + 0) * 4 + w4] = s;
            rB[((g * 8 + r) * 2 + 1) * 4 + w4] = q;
        }
    }
    __syncthreads();
    const float gv = g2[tl], bvx = be2[tl];
    #pragma unroll
    for (int r = 0; r < 8; r++) {
        float s = rB[((g * 8 + r) * 2 + 0) * 4 + 0] + rB[((g * 8 + r) * 2 + 0) * 4 + 1] +
                  rB[((g * 8 + r) * 2 + 0) * 4 + 2] + rB[((g * 8 + r) * 2 + 0) * 4 + 3];
        float q = rB[((g * 8 + r) * 2 + 1) * 4 + 0] + rB[((g * 8 + r) * 2 + 1) * 4 + 1] +
                  rB[((g * 8 + r) * 2 + 1) * 4 + 2] + rB[((g * 8 + r) * 2 + 1) * 4 + 3];
        float mu = s * invM;
        float inv = rsqrtf(q * invM - mu * mu + LN_EPSF);
        float v = fmaxf((acc[r] - mu) * inv * gv + bvx, 0.0f);
        int m = r0 + r;
        int tile = m >> 7, ml = m & 127;
        int idx = tile * 16384 + swz_idx(ml, tl);
        __nv_bfloat16 hh = __float2bfloat16(v);
        g_Ahi[idx] = hh;
        g_Alo[idx] = __float2bfloat16(v - __bfloat162float(hh));
    }
}

// =====================================================================
// GEMM (bf16x3 mma.sync, tile 128x80, 4m x 2n warp split)
// + warp-per-row einsum epilogue (basis via direct LDG).
// grid (64, 32). 256 threads, 2 CTAs/SM.
// =====================================================================
__global__ void __launch_bounds__(256, 2)
gemm_einsum_mma(const float* __restrict__ b3,
                float* __restrict__ out)
{
    extern __shared__ __align__(16) char smem[];
    const uint32_t sb = smem_u32(smem);
    const int tid  = threadIdx.x;
    const int wid  = tid >> 5, lane = tid & 31;
    const int ob   = blockIdx.x >> 1;     // o block (0..31)
    const int h    = blockIdx.x & 1;      // column half (80 cols)
    const int rt   = blockIdx.y;          // row tile (0..31)
    const int r0   = rt * 128;

    // ---- cp.async: A hi/lo (64KB), B half hi/lo (40KB), b3 slice
    {
        const char* sAh = (const char*)(g_Ahi + (size_t)rt * 16384);
        const char* sAl = (const char*)(g_Alo + (size_t)rt * 16384);
        const char* sBh = (const char*)(g_Bhi + (size_t)ob * 20480 + h * 10240);
        const char* sBl = (const char*)(g_Blo + (size_t)ob * 20480 + h * 10240);
        for (int i = tid; i < 2048; i += 256) {
            cp_async16(sb + OFF_A_HI + i * 16, sAh + i * 16);
            cp_async16(sb + OFF_A_LO + i * 16, sAl + i * 16);
        }
        for (int i = tid; i < 1280; i += 256) {
            cp_async16(sb + OFF_B_HI + i * 16, sBh + i * 16);
            cp_async16(sb + OFF_B_LO + i * 16, sBl + i * 16);
        }
        const char* b3p = (const char*)(b3 + ob * 160 + h * 80);
        if (tid < 20) cp_async16(sb + OFF_B3 + tid * 16, b3p + tid * 16);
        cp_commit();
    }
    cp_wait<0>();
    __syncthreads();

    // ---- MMA mainloop: warp = (mg 0..3: 32 rows) x (wn 0..1: 40 B-rows) ----
    const int mg = wid >> 1;
    const int wn = wid & 1;
    const int axor = lane & 7;
    const int ak   = lane >> 4;
    const int bk   = (lane >> 3) & 1;

    const uint32_t aAddr  = sb + OFF_A_HI + ((mg * 32 + (lane & 15)) << 8);
    const uint32_t bAddr4 = sb + OFF_B_HI +
        ((wn * 40 + ((lane >> 4) & 1) * 8 + (lane & 7)) << 8);
    const uint32_t bAddr2 = sb + OFF_B_HI + ((wn * 40 + 32 + (lane & 7)) << 8);

    float c0[5][4], c1[5][4];
    #pragma unroll
    for (int n = 0; n < 5; n++)
        #pragma unroll
        for (int q = 0; q < 4; q++) { c0[n][q] = 0.0f; c1[n][q] = 0.0f; }

    #pragma unroll
    for (int kk = 0; kk < 8; kk++) {
        uint32_t gA = (uint32_t)(((2 * kk + ak) ^ axor) << 4);
        uint32_t gB = (uint32_t)(((2 * kk + bk) ^ axor) << 4);
        uint32_t ah0[4], al0[4], ah1[4], al1[4];
        ldmx4(ah0, aAddr + gA);
        ldmx4(al0, aAddr + 32768 + gA);
        ldmx4(ah1, aAddr + 4096 + gA);
        ldmx4(al1, aAddr + 4096 + 32768 + gA);
        #pragma unroll
        for (int j2 = 0; j2 < 2; j2++) {
            uint32_t bh[4], bl[4];
            uint32_t ba = bAddr4 + j2 * 4096 + gB;
            ldmx4(bh, ba);
            ldmx4(bl, ba + 20480);
            mma16816(c0[2 * j2], ah0, bh[0], bh[1]);
            mma16816(c0[2 * j2], ah0, bl[0], bl[1]);
            mma16816(c0[2 * j2], al0, bh[0], bh[1]);
            mma16816(c0[2 * j2 + 1], ah0, bh[2], bh[3]);
            mma16816(c0[2 * j2 + 1], ah0, bl[2], bl[3]);
            mma16816(c0[2 * j2 + 1], al0, bh[2], bh[3]);
            mma16816(c1[2 * j2], ah1, bh[0], bh[1]);
            mma16816(c1[2 * j2], ah1, bl[0], bl[1]);
            mma16816(c1[2 * j2], al1, bh[0], bh[1]);
            mma16816(c1[2 * j2 + 1], ah1, bh[2], bh[3]);
            mma16816(c1[2 * j2 + 1], ah1, bl[2], bl[3]);
            mma16816(c1[2 * j2 + 1], al1, bh[2], bh[3]);
        }
        {
            uint32_t bh2[2], bl2[2];
            ldmx2(bh2, bAddr2 + gB);
            ldmx2(bl2, bAddr2 + 20480 + gB);
            mma16816(c0[4], ah0, bh2[0], bh2[1]);
            mma16816(c0[4], ah0, bl2[0], bl2[1]);
            mma16816(c0[4], al0, bh2[0], bh2[1]);
            mma16816(c1[4], ah1, bh2[0], bh2[1]);
            mma16816(c1[4], ah1, bl2[0], bl2[1]);
            mma16816(c1[4], al1, bh2[0], bh2[1]);
        }
    }

    __syncthreads();   // all operand reads done; staging may overwrite

    // ---- stage C (+b3) to smem [128][SPC]
    float* stg = (float*)(smem + OFF_STGC);
    const float* sB3 = (const float*)(smem + OFF_B3);
    {
        const int rb = mg * 32 + (lane >> 2);
        #pragma unroll
        for (int mtl = 0; mtl < 2; mtl++) {
            int rlo = rb + mtl * 16;
            int rhi = rlo + 8;
            float (*cc)[4] = mtl ? c1 : c0;
            #pragma unroll
            for (int ntl = 0; ntl < 5; ntl++) {
                int col = wn * 40 + ntl * 8 + 2 * (lane & 3);
                float bA = sB3[col], bB = sB3[col + 1];
                stg[rlo * SPC + col]     = cc[ntl][0] + bA;
                stg[rlo * SPC + col + 1] = cc[ntl][1] + bB;
                stg[rhi * SPC + col]     = cc[ntl][2] + bA;
                stg[rhi * SPC + col + 1] = cc[ntl][3] + bB;
            }
        }
    }
    __syncthreads();

    // ---- warp-per-row einsum epilogue; basis via broadcast LDG
    int colp[3], ip[3], mp[3];
    #pragma unroll
    for (int p = 0; p < 3; p++) {
        colp[p] = p * 32 + lane;
        ip[p]   = colp[p] / 5;
        mp[p]   = colp[p] - 5 * ip[p];
    }
    const int blane = (lane < 25) ? lane : 0;
    const float* basT = g_basP + ((size_t)rt << 14);

    #pragma unroll 1
    for (int rr = 0; rr < 16; rr++) {
        const int rloc = wid * 16 + rr;
        const float* Rrow = stg + rloc * SPC;
        float Rf[3][5];
        #pragma unroll
        for (int p = 0; p < 3; p++)
            #pragma unroll
            for (int f = 0; f < 5; f++)
                Rf[p][f] = Rrow[ip[p] * 5 + f];

        const float* basRow = basT + rloc * 128;
        float bv[5];
        #pragma unroll
        for (int d = 0; d < 5; d++) bv[d] = basRow[d * 25 + blane];

        float* outR = out + (size_t)(r0 + rloc) * 25600 + (size_t)ob * 800 + h * 80;
        #pragma unroll
        for (int d = 0; d < 5; d++) {
            #pragma unroll
            for (int p = 0; p < 3; p++) {
                float a = 0.0f;
                #pragma unroll
                for (int f = 0; f < 5; f++) {
                    float bf = __shfl_sync(0xffffffffu, bv[d], mp[p] * 5 + f);
                    a = fmaf(Rf[p][f], bf, a);
                }
                if (p < 2 || lane < 16)
                    outR[d * 160 + colp[p]] = a;
            }
        }
    }
}

extern "C" void kernel_launch(void* const* d_in, const int* in_sizes, int n_in,
                              void* d_out, int out_size)
{
    const float* feat  = (const float*)d_in[0];
    const float* basis = (const float*)d_in[1];
    const float* W1    = (const float*)d_in[2];
    const float* b1    = (const float*)d_in[3];
    const float* g1    = (const float*)d_in[4];
    const float* be1   = (const float*)d_in[5];
    const float* W2    = (const float*)d_in[6];
    const float* b2    = (const float*)d_in[7];
    const float* g2    = (const float*)d_in[8];
    const float* be2   = (const float*)d_in[9];
    const float* W3    = (const float*)d_in[10];
    const float* b3    = (const float*)d_in[11];
    float* out = (float*)d_out;

    cudaFuncSetAttribute(gemm_einsum_mma,
                         cudaFuncAttributeMaxDynamicSharedMemorySize, SMEM_TOTAL);

    prep_kernel<<<416, 256>>>(feat, basis, W1, b1, g1, be1, W2, b2, g2, be2, W3);

    dim3 grid(NOBLK * 2, MTILES);   // (64, 32)
    gemm_einsum_mma<<<grid, 256, SMEM_TOTAL>>>(b3, out);
}